// round 5
// baseline (speedup 1.0000x reference)
#include <cuda_runtime.h>
#include <cuda_fp16.h>
#include <cstdint>

#define NB   4
#define CIN  32
#define CC   64
#define V3   32768
#define NG   8
#define EPS  1e-5f

__device__ __align__(16) float g_pts[NB * CC * V3];
__device__ __align__(16) float g_vox_a[NB * V3 * CC];
__device__ __align__(16) float g_vox_b[NB * V3 * CC];
__device__ __align__(16) __half g_hi[NB * V3 * CC];
__device__ __align__(16) __half g_lo[NB * V3 * CC];
__device__ __align__(16) unsigned char g_wblob[884736];  // [conv][prec][tap][64x128B sw128]
__device__ int   g_cnt[NB * V3];
__device__ float g_bias[NB * CC];
__device__ float g_mu[NB * NG];
__device__ float g_rs[NB * NG];
__device__ float g_ps[1024];
__device__ float g_pq[1024];

__device__ __forceinline__ float siluf(float x) { return x / (1.f + __expf(-x)); }

__device__ __forceinline__ uint32_t s2u(const void* p) {
    uint32_t a;
    asm("{ .reg .u64 t; cvta.to.shared.u64 t, %1; cvt.u32.u64 %0, t; }" : "=r"(a) : "l"(p));
    return a;
}

#define LDSM4(R, addr) \
    asm volatile("ldmatrix.sync.aligned.m8n8.x4.shared.b16 {%0,%1,%2,%3}, [%4];" \
        : "=r"((R)[0]), "=r"((R)[1]), "=r"((R)[2]), "=r"((R)[3]) : "r"(addr))
#define LDSM4T(r0, r1, r2, r3, addr) \
    asm volatile("ldmatrix.sync.aligned.m8n8.x4.trans.shared.b16 {%0,%1,%2,%3}, [%4];" \
        : "=r"(r0), "=r"(r1), "=r"(r2), "=r"(r3) : "r"(addr))
#define MMA(dacc, A, B) \
    asm volatile("mma.sync.aligned.m16n8k16.row.col.f32.f16.f16.f32 " \
        "{%0,%1,%2,%3}, {%4,%5,%6,%7}, {%8,%9}, {%0,%1,%2,%3};" \
        : "+f"((dacc)[0]), "+f"((dacc)[1]), "+f"((dacc)[2]), "+f"((dacc)[3]) \
        : "r"((A)[0]), "r"((A)[1]), "r"((A)[2]), "r"((A)[3]), "r"((B)[0]), "r"((B)[1]))

__device__ __forceinline__ void hi_lo(float v, unsigned short& h, unsigned short& l) {
    __half hb = __float2half_rn(v);
    h = __half_as_ushort(hb);
    l = __half_as_ushort(__float2half_rn(v - __half2float(hb)));
}

// ---------------- small kernels ----------------
__global__ void k_bias(const float* __restrict__ te_, const float* __restrict__ wt,
                       const float* __restrict__ bt) {
    __shared__ float te[256];
    int b = blockIdx.x, o = threadIdx.x;
    for (int i = o; i < 256; i += 64) te[i] = te_[b * 256 + i];
    __syncthreads();
    float s = bt[o];
    #pragma unroll 8
    for (int t = 0; t < 256; t++) s += te[t] * wt[o * 256 + t];
    g_bias[b * CC + o] = s;
}

__global__ void __launch_bounds__(128) k_pw_in(const float* __restrict__ f, const float* __restrict__ w) {
    __shared__ float sw[CIN * CC];
    for (int i = threadIdx.x; i < CIN * CC; i += 128) sw[(i & 31) * CC + (i >> 5)] = w[i];
    __syncthreads();
    int p = blockIdx.x * 128 + threadIdx.x;
    int b = p >> 15, n = p & 32767;
    float acc[CC];
    #pragma unroll
    for (int o = 0; o < CC; o++) acc[o] = 0.f;
    for (int c = 0; c < CIN; c++) {
        float x = f[((b * CIN + c) << 15) + n];
        const float4* wr = (const float4*)(sw + c * CC);
        #pragma unroll
        for (int q = 0; q < 16; q++) {
            float4 ww = wr[q];
            acc[q*4+0] += x*ww.x; acc[q*4+1] += x*ww.y; acc[q*4+2] += x*ww.z; acc[q*4+3] += x*ww.w;
        }
    }
    #pragma unroll
    for (int o = 0; o < CC; o++) g_pts[((b * CC + o) << 15) + n] = acc[o];
}

// ---- two-stage GN stats ----
__global__ void __launch_bounds__(256) k_st1(const float* __restrict__ buf) {   // (b,c,n)
    __shared__ float ss[256], sq2[256];
    int bg = blockIdx.x >> 5, ch = blockIdx.x & 31;
    const float4* p = (const float4*)(buf + (size_t)bg * 262144 + ch * 8192);
    float s = 0.f, q = 0.f;
    for (int i = threadIdx.x; i < 2048; i += 256) {
        float4 v = p[i];
        s += v.x + v.y + v.z + v.w;
        q += v.x*v.x + v.y*v.y + v.z*v.z + v.w*v.w;
    }
    ss[threadIdx.x] = s; sq2[threadIdx.x] = q; __syncthreads();
    for (int st = 128; st > 0; st >>= 1) {
        if (threadIdx.x < st) { ss[threadIdx.x] += ss[threadIdx.x+st]; sq2[threadIdx.x] += sq2[threadIdx.x+st]; }
        __syncthreads();
    }
    if (threadIdx.x == 0) { g_ps[blockIdx.x] = ss[0]; g_pq[blockIdx.x] = sq2[0]; }
}

__global__ void __launch_bounds__(256) k_st1_vc(const float* __restrict__ buf) {  // (b,v,c)
    __shared__ float ss[256], sq2[256];
    int bg = blockIdx.x >> 5, ch = blockIdx.x & 31;
    int b = bg >> 3, g = bg & 7;
    const float4* base = (const float4*)(buf + ((size_t)b << 21) + (g << 3));
    float s = 0.f, q = 0.f;
    for (int i = threadIdx.x; i < 2048; i += 256) {
        int v = (ch << 10) + (i >> 1);
        float4 x = base[(size_t)v * 16 + (i & 1)];
        s += x.x + x.y + x.z + x.w;
        q += x.x*x.x + x.y*x.y + x.z*x.z + x.w*x.w;
    }
    ss[threadIdx.x] = s; sq2[threadIdx.x] = q; __syncthreads();
    for (int st = 128; st > 0; st >>= 1) {
        if (threadIdx.x < st) { ss[threadIdx.x] += ss[threadIdx.x+st]; sq2[threadIdx.x] += sq2[threadIdx.x+st]; }
        __syncthreads();
    }
    if (threadIdx.x == 0) { g_ps[blockIdx.x] = ss[0]; g_pq[blockIdx.x] = sq2[0]; }
}

__global__ void k_st2() {
    int bg = threadIdx.x;
    if (bg < 32) {
        float s = 0.f, q = 0.f;
        #pragma unroll
        for (int c = 0; c < 32; c++) { s += g_ps[bg * 32 + c]; q += g_pq[bg * 32 + c]; }
        float m = s * (1.f / 262144.f);
        float v = q * (1.f / 262144.f) - m * m;
        g_mu[bg] = m; g_rs[bg] = rsqrtf(v + EPS);
    }
}

__global__ void k_zero() {
    int t = blockIdx.x * 256 + threadIdx.x;           // 524288 threads, 4 float4 each
    float4 z = make_float4(0.f, 0.f, 0.f, 0.f);
    float4* p = (float4*)g_vox_a;
    p[t] = z; p[t + 524288] = z; p[t + 1048576] = z; p[t + 1572864] = z;
    if (t < 32768) ((int4*)g_cnt)[t] = make_int4(0, 0, 0, 0);
}

__global__ void __launch_bounds__(128) k_scatter(const float* __restrict__ coords,
                                                 const float* __restrict__ gg,
                                                 const float* __restrict__ gb) {
    int p = blockIdx.x * 128 + threadIdx.x;
    int b = p >> 15, n = p & 32767;
    int ix = min(max(__float2int_rd(coords[p*3+0]*31.f), 0), 31);
    int iy = min(max(__float2int_rd(coords[p*3+1]*31.f), 0), 31);
    int iz = min(max(__float2int_rd(coords[p*3+2]*31.f), 0), 31);
    int flat = (ix << 10) + (iy << 5) + iz;
    atomicAdd(&g_cnt[(b << 15) + flat], 1);
    float* dst = g_vox_a + ((size_t)((b << 15) + flat) << 6);
    #pragma unroll 4
    for (int c = 0; c < CC; c++) {
        int bg = b * NG + (c >> 3);
        float x = g_pts[((b * CC + c) << 15) + n];
        x = siluf((x - g_mu[bg]) * g_rs[bg] * gg[c] + gb[c]) + g_bias[b * CC + c];
        atomicAdd(dst + c, x);
    }
}

__global__ void k_voxfin_cvt() {
    int idx = blockIdx.x * 256 + threadIdx.x;           // b*V3+v
    int b = idx >> 15;
    float inv = 1.f / (float)max(g_cnt[idx], 1);
    const float4* s4 = (const float4*)(g_vox_a + ((size_t)idx << 6));
    uint4* h4 = (uint4*)(g_hi + ((size_t)idx << 6));
    uint4* l4 = (uint4*)(g_lo + ((size_t)idx << 6));
    const float* bias = g_bias + b * CC;
    #pragma unroll
    for (int q = 0; q < 8; q++) {
        float4 v0 = s4[q*2], v1 = s4[q*2+1];
        float x[8] = {v0.x,v0.y,v0.z,v0.w,v1.x,v1.y,v1.z,v1.w};
        unsigned short hs[8], ls[8];
        #pragma unroll
        for (int j = 0; j < 8; j++) hi_lo(x[j]*inv + bias[q*8+j], hs[j], ls[j]);
        h4[q] = make_uint4(hs[0]|((uint32_t)hs[1]<<16), hs[2]|((uint32_t)hs[3]<<16),
                           hs[4]|((uint32_t)hs[5]<<16), hs[6]|((uint32_t)hs[7]<<16));
        l4[q] = make_uint4(ls[0]|((uint32_t)ls[1]<<16), ls[2]|((uint32_t)ls[3]<<16),
                           ls[4]|((uint32_t)ls[5]<<16), ls[6]|((uint32_t)ls[7]<<16));
    }
}

__global__ void k_gnsilu_cvt(const float* __restrict__ src,
                             const float* __restrict__ gg, const float* __restrict__ gb) {
    int idx = blockIdx.x * 256 + threadIdx.x;
    int b = idx >> 15;
    const float4* s4 = (const float4*)(src + ((size_t)idx << 6));
    uint4* h4 = (uint4*)(g_hi + ((size_t)idx << 6));
    uint4* l4 = (uint4*)(g_lo + ((size_t)idx << 6));
    #pragma unroll
    for (int q = 0; q < 8; q++) {
        float mu = g_mu[b*NG+q], rs = g_rs[b*NG+q];
        float4 v0 = s4[q*2], v1 = s4[q*2+1];
        float x[8] = {v0.x,v0.y,v0.z,v0.w,v1.x,v1.y,v1.z,v1.w};
        unsigned short hs[8], ls[8];
        #pragma unroll
        for (int j = 0; j < 8; j++) {
            int c = q*8+j;
            hi_lo(siluf((x[j]-mu)*rs*gg[c] + gb[c]), hs[j], ls[j]);
        }
        h4[q] = make_uint4(hs[0]|((uint32_t)hs[1]<<16), hs[2]|((uint32_t)hs[3]<<16),
                           hs[4]|((uint32_t)hs[5]<<16), hs[6]|((uint32_t)hs[7]<<16));
        l4[q] = make_uint4(ls[0]|((uint32_t)ls[1]<<16), ls[2]|((uint32_t)ls[3]<<16),
                           ls[4]|((uint32_t)ls[5]<<16), ls[6]|((uint32_t)ls[7]<<16));
    }
}

__global__ void k_gnsilu_vc(float* __restrict__ buf,
                            const float* __restrict__ gg, const float* __restrict__ gb) {
    int idx = blockIdx.x * 256 + threadIdx.x;
    int b = idx >> 15;
    float4* s4 = (float4*)(buf + ((size_t)idx << 6));
    #pragma unroll
    for (int q = 0; q < 8; q++) {
        float mu = g_mu[b*NG+q], rs = g_rs[b*NG+q];
        float4 v0 = s4[q*2], v1 = s4[q*2+1];
        float x[8] = {v0.x,v0.y,v0.z,v0.w,v1.x,v1.y,v1.z,v1.w};
        #pragma unroll
        for (int j = 0; j < 8; j++) {
            int c = q*8+j;
            x[j] = siluf((x[j]-mu)*rs*gg[c] + gb[c]);
        }
        s4[q*2]   = make_float4(x[0],x[1],x[2],x[3]);
        s4[q*2+1] = make_float4(x[4],x[5],x[6],x[7]);
    }
}

// wblob: B matrix per tap: row k = c_in (64 rows x 128B), col n = o_out, SW128 swizzled.
__global__ void k_wprep(const float* __restrict__ w1, const float* __restrict__ w2) {
    int i = blockIdx.x * 256 + threadIdx.x;
    if (i >= 221184) return;
    int conv = i / 110592, r = i - conv * 110592;
    int o = r / 1728, r2 = r - o * 1728;
    int c = r2 / 27, t = r2 - c * 27;
    float w = conv ? w2[r] : w1[r];
    __half h = __float2half_rn(w);
    __half l = __float2half_rn(w - __half2float(h));
    uint32_t off = (uint32_t)c * 128 + (uint32_t)o * 2;
    uint32_t swo = off ^ ((off >> 3) & 0x70);
    size_t base = (size_t)conv * 442368;
    *(__half*)(g_wblob + base + (size_t)t * 8192 + swo) = h;
    *(__half*)(g_wblob + base + 221184 + (size_t)t * 8192 + swo) = l;
}

// ---------------- HMMA conv: M=256 (8y x 32x), 256 threads ----------------
// smem: A hi [0, 43520) = 340 rows(10y x 34x) x 128B; A lo [43520, 87040);
//       W hi [87040, 95232); W lo [95232, 103424)
#define CONV_SMEM 103424

__global__ void __launch_bounds__(256)
k_conv_mma(const __half* __restrict__ hi, const __half* __restrict__ lo,
           const unsigned char* __restrict__ wblob, float* __restrict__ out) {
    extern __shared__ char smem[];
    const uint32_t sb = s2u(smem);
    const int tid = threadIdx.x, wid = tid >> 5, lane = tid & 31;
    int t = blockIdx.x;                     // b*128 + d*4 + hq
    int b = t >> 7, tt = t & 127;
    int d = tt >> 2, h0 = (tt & 3) << 3;
    int r0 = t << 8;                        // base output voxel index (b,v)

    float acc[2][8][4];
    #pragma unroll
    for (int mt = 0; mt < 2; mt++)
        #pragma unroll
        for (int nt = 0; nt < 8; nt++)
            #pragma unroll
            for (int k = 0; k < 4; k++) acc[mt][nt][k] = 0.f;

    const int a_r  = lane & 15;
    const int a_cb = (lane >> 4) << 4;

    for (int dz = 0; dz < 3; dz++) {
        int dp = d + dz - 1;
        if ((unsigned)dp >= 32u) continue;
        __syncthreads();
        // stage A slab: rows = yy*34 + (x+1), yy = y - h0 + 1 in 0..9, x in -1..32
        for (int i = tid; i < 5440; i += 256) {
            int prec = (i >= 2720) ? 1 : 0;
            int j = prec ? i - 2720 : i;
            int row = j >> 3, c16 = j & 7;
            int yyl = row / 34, xl = row - yyl * 34;
            int hh = h0 + yyl - 1, ww = xl - 1;
            uint4 v = make_uint4(0, 0, 0, 0);
            if ((unsigned)hh < 32u && (unsigned)ww < 32u) {
                size_t g = ((size_t)((b << 15) + (dp << 10) + (hh << 5) + ww) << 3) + c16;
                v = prec ? ((const uint4*)lo)[g] : ((const uint4*)hi)[g];
            }
            *(uint4*)(smem + prec * 43520 + row * 128 + ((c16 << 4) ^ ((row & 7) << 4))) = v;
        }
        for (int t9 = 0; t9 < 9; t9++) {
            int tap = dz * 9 + t9;
            __syncthreads();
            {   // stage W (pre-swizzled): 512 uint4 hi + 512 uint4 lo
                const uint4* wsh = (const uint4*)(wblob + (size_t)tap * 8192);
                const uint4* wsl = (const uint4*)(wblob + 221184 + (size_t)tap * 8192);
                uint4* wd = (uint4*)(smem + 87040);
                wd[tid] = wsh[tid];
                wd[256 + tid] = wsh[256 + tid];
                wd[512 + tid] = wsl[tid];
                wd[768 + tid] = wsl[256 + tid];
            }
            __syncthreads();
            int dy = t9 / 3 - 1, dx = t9 - (t9 / 3) * 3 - 1;
            int srow_base = (wid + dy + 1) * 34 + (dx + 1);
            #pragma unroll
            for (int ks = 0; ks < 4; ks++) {
                uint32_t Ah[2][4], Al[2][4], Bh[8][2], Bl[8][2];
                int cb = (ks << 5) + a_cb;
                #pragma unroll
                for (int mt = 0; mt < 2; mt++) {
                    int row = srow_base + (mt << 4) + a_r;
                    uint32_t sw = (uint32_t)(cb ^ ((row & 7) << 4));
                    uint32_t addr = sb + (uint32_t)row * 128 + sw;
                    LDSM4(Ah[mt], addr);
                    LDSM4(Al[mt], addr + 43520);
                }
                {
                    int krow = (ks << 4) + (lane & 15);
                    uint32_t rbase = sb + 87040 + (uint32_t)krow * 128;
                    uint32_t xr = (uint32_t)((krow & 7) << 4);
                    int nbl = (lane >> 4) << 4;
                    #pragma unroll
                    for (int nt4 = 0; nt4 < 4; nt4++) {
                        uint32_t nb = (uint32_t)((nt4 << 5) + nbl);
                        uint32_t addr = rbase + (nb ^ xr);
                        LDSM4T(Bh[nt4*2][0], Bh[nt4*2][1], Bh[nt4*2+1][0], Bh[nt4*2+1][1], addr);
                        LDSM4T(Bl[nt4*2][0], Bl[nt4*2][1], Bl[nt4*2+1][0], Bl[nt4*2+1][1], addr + 8192);
                    }
                }
                #pragma unroll
                for (int mt = 0; mt < 2; mt++)
                    #pragma unroll
                    for (int nt = 0; nt < 8; nt++) {
                        MMA(acc[mt][nt], Ah[mt], Bh[nt]);
                        MMA(acc[mt][nt], Ah[mt], Bl[nt]);
                        MMA(acc[mt][nt], Al[mt], Bh[nt]);
                    }
            }
        }
    }
    // epilogue: write fp32 (b,v,c)
    int g = lane >> 2, tg = lane & 3;
    #pragma unroll
    for (int mt = 0; mt < 2; mt++) {
        int v0 = r0 + (wid << 5) + (mt << 4) + g;
        #pragma unroll
        for (int nt = 0; nt < 8; nt++) {
            int c = (nt << 3) + tg * 2;
            float* o = out + ((size_t)v0 << 6) + c;
            o[0] = acc[mt][nt][0];
            o[1] = acc[mt][nt][1];
            o[512] = acc[mt][nt][2];      // row +8 -> +8*64 floats
            o[513] = acc[mt][nt][3];
        }
    }
}

// ---------------- devox + fuse ----------------
__global__ void __launch_bounds__(128) k_devox(const float* __restrict__ coords,
                                               const float* __restrict__ wfuse) {
    __shared__ float swf[CC * CC];
    for (int i = threadIdx.x; i < CC * CC; i += 128) swf[(i & 63) * CC + (i >> 6)] = wfuse[i];
    __syncthreads();
    int p = blockIdx.x * 128 + threadIdx.x;
    int b = p >> 15, n = p & 32767;
    float cx = coords[p*3+0]*31.f, cy = coords[p*3+1]*31.f, cz = coords[p*3+2]*31.f;
    float fx = cx - floorf(cx), fy = cy - floorf(cy), fz = cz - floorf(cz);
    int x0 = min(max(__float2int_rd(cx),0),31), x1 = min(x0+1,31);
    int y0 = min(max(__float2int_rd(cy),0),31), y1 = min(y0+1,31);
    int z0 = min(max(__float2int_rd(cz),0),31), z1 = min(z0+1,31);
    const float4* base[8]; float wk[8]; int k = 0;
    #pragma unroll
    for (int ddx = 0; ddx < 2; ddx++)
        #pragma unroll
        for (int ddy = 0; ddy < 2; ddy++)
            #pragma unroll
            for (int ddz = 0; ddz < 2; ddz++) {
                int X = ddx?x1:x0, Y = ddy?y1:y0, Z = ddz?z1:z0;
                wk[k] = (ddx?fx:1.f-fx)*(ddy?fy:1.f-fy)*(ddz?fz:1.f-fz);
                base[k] = (const float4*)(g_vox_b + (((size_t)(b<<15) + ((X<<10)+(Y<<5)+Z)) << 6));
                k++;
            }
    float acc[CC];
    #pragma unroll
    for (int o = 0; o < CC; o++) acc[o] = 0.f;
    #pragma unroll
    for (int c4 = 0; c4 < 16; c4++) {
        float r[32];
        #pragma unroll
        for (int kk = 0; kk < 8; kk++) {
            float4 v = __ldg(base[kk] + c4);
            r[kk*4] = v.x; r[kk*4+1] = v.y; r[kk*4+2] = v.z; r[kk*4+3] = v.w;
        }
        #pragma unroll
        for (int j = 0; j < 4; j++) {
            float dd = r[j]*wk[0] + r[4+j]*wk[1] + r[8+j]*wk[2] + r[12+j]*wk[3]
                     + r[16+j]*wk[4] + r[20+j]*wk[5] + r[24+j]*wk[6] + r[28+j]*wk[7];
            const float4* wr = (const float4*)(swf + (c4*4+j)*CC);
            #pragma unroll
            for (int q = 0; q < 16; q++) {
                float4 ww = wr[q];
                acc[q*4+0] += dd*ww.x; acc[q*4+1] += dd*ww.y; acc[q*4+2] += dd*ww.z; acc[q*4+3] += dd*ww.w;
            }
        }
    }
    #pragma unroll
    for (int o = 0; o < CC; o++) g_pts[((b * CC + o) << 15) + n] = acc[o];
}

__global__ void __launch_bounds__(128) k_final(const float* __restrict__ f,
                                               const float* __restrict__ wskip,
                                               const float* __restrict__ gg,
                                               const float* __restrict__ gb,
                                               float* __restrict__ out) {
    __shared__ float sw[CIN * CC];
    __shared__ float sg[64], sb2[64];
    for (int i = threadIdx.x; i < CIN * CC; i += 128) sw[(i & 31) * CC + (i >> 5)] = wskip[i];
    if (threadIdx.x < 64) { sg[threadIdx.x] = gg[threadIdx.x]; sb2[threadIdx.x] = gb[threadIdx.x]; }
    __syncthreads();
    int p = blockIdx.x * 128 + threadIdx.x;
    int b = p >> 15, n = p & 32767;
    float acc[CC];
    #pragma unroll
    for (int o = 0; o < CC; o++) acc[o] = 0.f;
    for (int c = 0; c < CIN; c++) {
        float x = f[((b * CIN + c) << 15) + n];
        const float4* wr = (const float4*)(sw + c * CC);
        #pragma unroll
        for (int q = 0; q < 16; q++) {
            float4 ww = wr[q];
            acc[q*4+0] += x*ww.x; acc[q*4+1] += x*ww.y; acc[q*4+2] += x*ww.z; acc[q*4+3] += x*ww.w;
        }
    }
    #pragma unroll
    for (int o = 0; o < CC; o++) {
        int bg = b * NG + (o >> 3);
        float v = g_pts[((b * CC + o) << 15) + n];
        v = (v - g_mu[bg]) * g_rs[bg] * sg[o] + sb2[o];
        out[((b * CC + o) << 15) + n] = siluf(v) + acc[o];
    }
}

// ---------------------------------------------------------------------------
extern "C" void kernel_launch(void* const* d_in, const int* in_sizes, int n_in,
                              void* d_out, int out_size) {
    const float* feats  = (const float*)d_in[0];
    const float* coords = (const float*)d_in[1];
    const float* t_emb  = (const float*)d_in[2];
    const float* w_in   = (const float*)d_in[3];
    const float* gn1_g  = (const float*)d_in[4];
    const float* gn1_b  = (const float*)d_in[5];
    const float* w_time = (const float*)d_in[6];
    const float* b_time = (const float*)d_in[7];
    const float* w_vox1 = (const float*)d_in[8];
    const float* gn2_g  = (const float*)d_in[9];
    const float* gn2_b  = (const float*)d_in[10];
    const float* w_vox2 = (const float*)d_in[11];
    const float* gn3_g  = (const float*)d_in[12];
    const float* gn3_b  = (const float*)d_in[13];
    const float* w_fuse = (const float*)d_in[14];
    const float* gn4_g  = (const float*)d_in[15];
    const float* gn4_b  = (const float*)d_in[16];
    const float* w_skip = (const float*)d_in[17];
    float* out = (float*)d_out;

    float *pts, *va, *vb;
    __half *hp, *lp;
    unsigned char* wb;
    cudaGetSymbolAddress((void**)&pts, g_pts);
    cudaGetSymbolAddress((void**)&va, g_vox_a);
    cudaGetSymbolAddress((void**)&vb, g_vox_b);
    cudaGetSymbolAddress((void**)&hp, g_hi);
    cudaGetSymbolAddress((void**)&lp, g_lo);
    cudaGetSymbolAddress((void**)&wb, g_wblob);

    static int attr_set = 0;
    if (!attr_set) {
        cudaFuncSetAttribute(k_conv_mma, cudaFuncAttributeMaxDynamicSharedMemorySize, CONV_SMEM);
        attr_set = 1;
    }

    k_bias<<<NB, 64>>>(t_emb, w_time, b_time);
    k_wprep<<<864, 256>>>(w_vox1, w_vox2);
    k_pw_in<<<1024, 128>>>(feats, w_in);
    k_st1<<<1024, 256>>>(pts);  k_st2<<<1, 32>>>();
    k_zero<<<2048, 256>>>();
    k_scatter<<<1024, 128>>>(coords, gn1_g, gn1_b);
    k_voxfin_cvt<<<512, 256>>>();
    k_conv_mma<<<512, 256, CONV_SMEM>>>(hp, lp, wb, va);
    k_st1_vc<<<1024, 256>>>(va);  k_st2<<<1, 32>>>();
    k_gnsilu_cvt<<<512, 256>>>(va, gn2_g, gn2_b);
    k_conv_mma<<<512, 256, CONV_SMEM>>>(hp, lp, wb + 442368, vb);
    k_st1_vc<<<1024, 256>>>(vb);  k_st2<<<1, 32>>>();
    k_gnsilu_vc<<<512, 256>>>(vb, gn3_g, gn3_b);
    k_devox<<<1024, 128>>>(coords, w_fuse);
    k_st1<<<1024, 256>>>(pts);  k_st2<<<1, 32>>>();
    k_final<<<1024, 128>>>(feats, w_skip, gn4_g, gn4_b, out);
}

// round 6
// speedup vs baseline: 1.1714x; 1.1714x over previous
#include <cuda_runtime.h>
#include <cuda_fp16.h>
#include <cstdint>

#define NB   4
#define CIN  32
#define CC   64
#define V3   32768
#define NG   8
#define EPS  1e-5f

__device__ __align__(16) float g_pts[NB * CC * V3];
__device__ __align__(16) float g_vox_a[NB * V3 * CC];
__device__ __align__(16) float g_vox_b[NB * V3 * CC];
__device__ __align__(16) __half g_hi[NB * V3 * CC];
__device__ __align__(16) __half g_lo[NB * V3 * CC];
__device__ __align__(16) unsigned char g_wblob[884736];  // [conv][prec][tap][64x128B sw128]
__device__ int   g_cnt[NB * V3];
__device__ float g_bias[NB * CC];
__device__ float g_mu[NB * NG];
__device__ float g_rs[NB * NG];
__device__ float g_ps[1024];
__device__ float g_pq[1024];

__device__ __forceinline__ float siluf(float x) { return x / (1.f + __expf(-x)); }

__device__ __forceinline__ uint32_t s2u(const void* p) {
    uint32_t a;
    asm("{ .reg .u64 t; cvta.to.shared.u64 t, %1; cvt.u32.u64 %0, t; }" : "=r"(a) : "l"(p));
    return a;
}

#define LDSM4(R, addr) \
    asm volatile("ldmatrix.sync.aligned.m8n8.x4.shared.b16 {%0,%1,%2,%3}, [%4];" \
        : "=r"((R)[0]), "=r"((R)[1]), "=r"((R)[2]), "=r"((R)[3]) : "r"(addr))
#define LDSM4T(r0, r1, r2, r3, addr) \
    asm volatile("ldmatrix.sync.aligned.m8n8.x4.trans.shared.b16 {%0,%1,%2,%3}, [%4];" \
        : "=r"(r0), "=r"(r1), "=r"(r2), "=r"(r3) : "r"(addr))
#define MMA(dacc, A, B) \
    asm volatile("mma.sync.aligned.m16n8k16.row.col.f32.f16.f16.f32 " \
        "{%0,%1,%2,%3}, {%4,%5,%6,%7}, {%8,%9}, {%0,%1,%2,%3};" \
        : "+f"((dacc)[0]), "+f"((dacc)[1]), "+f"((dacc)[2]), "+f"((dacc)[3]) \
        : "r"((A)[0]), "r"((A)[1]), "r"((A)[2]), "r"((A)[3]), "r"((B)[0]), "r"((B)[1]))

__device__ __forceinline__ void hi_lo(float v, unsigned short& h, unsigned short& l) {
    __half hb = __float2half_rn(v);
    h = __half_as_ushort(hb);
    l = __half_as_ushort(__float2half_rn(v - __half2float(hb)));
}

// ---------------- small kernels ----------------
__global__ void k_bias(const float* __restrict__ te_, const float* __restrict__ wt,
                       const float* __restrict__ bt) {
    __shared__ float te[256];
    int b = blockIdx.x, o = threadIdx.x;
    for (int i = o; i < 256; i += 64) te[i] = te_[b * 256 + i];
    __syncthreads();
    float s = bt[o];
    #pragma unroll 8
    for (int t = 0; t < 256; t++) s += te[t] * wt[o * 256 + t];
    g_bias[b * CC + o] = s;
}

__global__ void __launch_bounds__(128) k_pw_in(const float* __restrict__ f, const float* __restrict__ w) {
    __shared__ float sw[CIN * CC];
    for (int i = threadIdx.x; i < CIN * CC; i += 128) sw[(i & 31) * CC + (i >> 5)] = w[i];
    __syncthreads();
    int p = blockIdx.x * 128 + threadIdx.x;
    int b = p >> 15, n = p & 32767;
    float acc[CC];
    #pragma unroll
    for (int o = 0; o < CC; o++) acc[o] = 0.f;
    for (int c = 0; c < CIN; c++) {
        float x = f[((b * CIN + c) << 15) + n];
        const float4* wr = (const float4*)(sw + c * CC);
        #pragma unroll
        for (int q = 0; q < 16; q++) {
            float4 ww = wr[q];
            acc[q*4+0] += x*ww.x; acc[q*4+1] += x*ww.y; acc[q*4+2] += x*ww.z; acc[q*4+3] += x*ww.w;
        }
    }
    #pragma unroll
    for (int o = 0; o < CC; o++) g_pts[((b * CC + o) << 15) + n] = acc[o];
}

// ---- two-stage GN stats ----
__global__ void __launch_bounds__(256) k_st1(const float* __restrict__ buf) {   // (b,c,n)
    __shared__ float ss[256], sq2[256];
    int bg = blockIdx.x >> 5, ch = blockIdx.x & 31;
    const float4* p = (const float4*)(buf + (size_t)bg * 262144 + ch * 8192);
    float s = 0.f, q = 0.f;
    for (int i = threadIdx.x; i < 2048; i += 256) {
        float4 v = p[i];
        s += v.x + v.y + v.z + v.w;
        q += v.x*v.x + v.y*v.y + v.z*v.z + v.w*v.w;
    }
    ss[threadIdx.x] = s; sq2[threadIdx.x] = q; __syncthreads();
    for (int st = 128; st > 0; st >>= 1) {
        if (threadIdx.x < st) { ss[threadIdx.x] += ss[threadIdx.x+st]; sq2[threadIdx.x] += sq2[threadIdx.x+st]; }
        __syncthreads();
    }
    if (threadIdx.x == 0) { g_ps[blockIdx.x] = ss[0]; g_pq[blockIdx.x] = sq2[0]; }
}

__global__ void __launch_bounds__(256) k_st1_vc(const float* __restrict__ buf) {  // (b,v,c)
    __shared__ float ss[256], sq2[256];
    int bg = blockIdx.x >> 5, ch = blockIdx.x & 31;
    int b = bg >> 3, g = bg & 7;
    const float4* base = (const float4*)(buf + ((size_t)b << 21) + (g << 3));
    float s = 0.f, q = 0.f;
    for (int i = threadIdx.x; i < 2048; i += 256) {
        int v = (ch << 10) + (i >> 1);
        float4 x = base[(size_t)v * 16 + (i & 1)];
        s += x.x + x.y + x.z + x.w;
        q += x.x*x.x + x.y*x.y + x.z*x.z + x.w*x.w;
    }
    ss[threadIdx.x] = s; sq2[threadIdx.x] = q; __syncthreads();
    for (int st = 128; st > 0; st >>= 1) {
        if (threadIdx.x < st) { ss[threadIdx.x] += ss[threadIdx.x+st]; sq2[threadIdx.x] += sq2[threadIdx.x+st]; }
        __syncthreads();
    }
    if (threadIdx.x == 0) { g_ps[blockIdx.x] = ss[0]; g_pq[blockIdx.x] = sq2[0]; }
}

__global__ void k_st2() {
    int bg = threadIdx.x;
    if (bg < 32) {
        float s = 0.f, q = 0.f;
        #pragma unroll
        for (int c = 0; c < 32; c++) { s += g_ps[bg * 32 + c]; q += g_pq[bg * 32 + c]; }
        float m = s * (1.f / 262144.f);
        float v = q * (1.f / 262144.f) - m * m;
        g_mu[bg] = m; g_rs[bg] = rsqrtf(v + EPS);
    }
}

__global__ void k_zero() {
    int t = blockIdx.x * 256 + threadIdx.x;           // 524288 threads, 4 float4 each
    float4 z = make_float4(0.f, 0.f, 0.f, 0.f);
    float4* p = (float4*)g_vox_a;
    p[t] = z; p[t + 524288] = z; p[t + 1048576] = z; p[t + 1572864] = z;
    if (t < 32768) ((int4*)g_cnt)[t] = make_int4(0, 0, 0, 0);
}

__global__ void __launch_bounds__(128) k_scatter(const float* __restrict__ coords,
                                                 const float* __restrict__ gg,
                                                 const float* __restrict__ gb) {
    int p = blockIdx.x * 128 + threadIdx.x;
    int b = p >> 15, n = p & 32767;
    int ix = min(max(__float2int_rd(coords[p*3+0]*31.f), 0), 31);
    int iy = min(max(__float2int_rd(coords[p*3+1]*31.f), 0), 31);
    int iz = min(max(__float2int_rd(coords[p*3+2]*31.f), 0), 31);
    int flat = (ix << 10) + (iy << 5) + iz;
    atomicAdd(&g_cnt[(b << 15) + flat], 1);
    float* dst = g_vox_a + ((size_t)((b << 15) + flat) << 6);
    #pragma unroll 4
    for (int c = 0; c < CC; c++) {
        int bg = b * NG + (c >> 3);
        float x = g_pts[((b * CC + c) << 15) + n];
        x = siluf((x - g_mu[bg]) * g_rs[bg] * gg[c] + gb[c]) + g_bias[b * CC + c];
        atomicAdd(dst + c, x);
    }
}

__global__ void k_voxfin_cvt() {
    int idx = blockIdx.x * 256 + threadIdx.x;           // b*V3+v
    int b = idx >> 15;
    float inv = 1.f / (float)max(g_cnt[idx], 1);
    const float4* s4 = (const float4*)(g_vox_a + ((size_t)idx << 6));
    uint4* h4 = (uint4*)(g_hi + ((size_t)idx << 6));
    uint4* l4 = (uint4*)(g_lo + ((size_t)idx << 6));
    const float* bias = g_bias + b * CC;
    #pragma unroll
    for (int q = 0; q < 8; q++) {
        float4 v0 = s4[q*2], v1 = s4[q*2+1];
        float x[8] = {v0.x,v0.y,v0.z,v0.w,v1.x,v1.y,v1.z,v1.w};
        unsigned short hs[8], ls[8];
        #pragma unroll
        for (int j = 0; j < 8; j++) hi_lo(x[j]*inv + bias[q*8+j], hs[j], ls[j]);
        h4[q] = make_uint4(hs[0]|((uint32_t)hs[1]<<16), hs[2]|((uint32_t)hs[3]<<16),
                           hs[4]|((uint32_t)hs[5]<<16), hs[6]|((uint32_t)hs[7]<<16));
        l4[q] = make_uint4(ls[0]|((uint32_t)ls[1]<<16), ls[2]|((uint32_t)ls[3]<<16),
                           ls[4]|((uint32_t)ls[5]<<16), ls[6]|((uint32_t)ls[7]<<16));
    }
}

__global__ void k_gnsilu_cvt(const float* __restrict__ src,
                             const float* __restrict__ gg, const float* __restrict__ gb) {
    int idx = blockIdx.x * 256 + threadIdx.x;
    int b = idx >> 15;
    const float4* s4 = (const float4*)(src + ((size_t)idx << 6));
    uint4* h4 = (uint4*)(g_hi + ((size_t)idx << 6));
    uint4* l4 = (uint4*)(g_lo + ((size_t)idx << 6));
    #pragma unroll
    for (int q = 0; q < 8; q++) {
        float mu = g_mu[b*NG+q], rs = g_rs[b*NG+q];
        float4 v0 = s4[q*2], v1 = s4[q*2+1];
        float x[8] = {v0.x,v0.y,v0.z,v0.w,v1.x,v1.y,v1.z,v1.w};
        unsigned short hs[8], ls[8];
        #pragma unroll
        for (int j = 0; j < 8; j++) {
            int c = q*8+j;
            hi_lo(siluf((x[j]-mu)*rs*gg[c] + gb[c]), hs[j], ls[j]);
        }
        h4[q] = make_uint4(hs[0]|((uint32_t)hs[1]<<16), hs[2]|((uint32_t)hs[3]<<16),
                           hs[4]|((uint32_t)hs[5]<<16), hs[6]|((uint32_t)hs[7]<<16));
        l4[q] = make_uint4(ls[0]|((uint32_t)ls[1]<<16), ls[2]|((uint32_t)ls[3]<<16),
                           ls[4]|((uint32_t)ls[5]<<16), ls[6]|((uint32_t)ls[7]<<16));
    }
}

__global__ void k_gnsilu_vc(float* __restrict__ buf,
                            const float* __restrict__ gg, const float* __restrict__ gb) {
    int idx = blockIdx.x * 256 + threadIdx.x;
    int b = idx >> 15;
    float4* s4 = (float4*)(buf + ((size_t)idx << 6));
    #pragma unroll
    for (int q = 0; q < 8; q++) {
        float mu = g_mu[b*NG+q], rs = g_rs[b*NG+q];
        float4 v0 = s4[q*2], v1 = s4[q*2+1];
        float x[8] = {v0.x,v0.y,v0.z,v0.w,v1.x,v1.y,v1.z,v1.w};
        #pragma unroll
        for (int j = 0; j < 8; j++) {
            int c = q*8+j;
            x[j] = siluf((x[j]-mu)*rs*gg[c] + gb[c]);
        }
        s4[q*2]   = make_float4(x[0],x[1],x[2],x[3]);
        s4[q*2+1] = make_float4(x[4],x[5],x[6],x[7]);
    }
}

// wblob: B matrix per tap: row k = c_in (64 rows x 128B), col n = o_out, SW128 swizzled.
__global__ void k_wprep(const float* __restrict__ w1, const float* __restrict__ w2) {
    int i = blockIdx.x * 256 + threadIdx.x;
    if (i >= 221184) return;
    int conv = i / 110592, r = i - conv * 110592;
    int o = r / 1728, r2 = r - o * 1728;
    int c = r2 / 27, t = r2 - c * 27;
    float w = conv ? w2[r] : w1[r];
    __half h = __float2half_rn(w);
    __half l = __float2half_rn(w - __half2float(h));
    uint32_t off = (uint32_t)c * 128 + (uint32_t)o * 2;
    uint32_t swo = off ^ ((off >> 3) & 0x70);
    size_t base = (size_t)conv * 442368;
    *(__half*)(g_wblob + base + (size_t)t * 8192 + swo) = h;
    *(__half*)(g_wblob + base + 221184 + (size_t)t * 8192 + swo) = l;
}

// ---------------- HMMA conv: mma.sync m16n8k16 f16, 3-pass hi/lo, M=128 ----------------
// smem: A slab hi [0, 26112) = 204 rows(6y x 34x) x 128B; A lo [26112, 52224);
//       W hi [52224, 60416); W lo [60416, 68608)
#define CONV_SMEM 68608

__global__ void __launch_bounds__(128)
k_conv_mma(const __half* __restrict__ hi, const __half* __restrict__ lo,
           const unsigned char* __restrict__ wblob, float* __restrict__ out) {
    extern __shared__ char smem[];
    const uint32_t sb = s2u(smem);
    const int tid = threadIdx.x, wid = tid >> 5, lane = tid & 31;
    int t = blockIdx.x;                     // b*256 + d*8 + hg
    int b = t >> 8, tt = t & 255;
    int d = tt >> 3, h0 = (tt & 7) << 2;
    int r0 = t << 7;                        // base output voxel index (b,v)

    float acc[2][8][4];
    #pragma unroll
    for (int mt = 0; mt < 2; mt++)
        #pragma unroll
        for (int nt = 0; nt < 8; nt++)
            #pragma unroll
            for (int k = 0; k < 4; k++) acc[mt][nt][k] = 0.f;

    const int a_r  = lane & 15;
    const int a_cb = (lane >> 4) << 4;

    for (int dz = 0; dz < 3; dz++) {
        int dp = d + dz - 1;
        if ((unsigned)dp >= 32u) continue;
        __syncthreads();
        // stage A slab: rows = (yy+1)*34 + (x+1), yy in -1..4, x in -1..32
        for (int i = tid; i < 3264; i += 128) {
            int prec = (i >= 1632) ? 1 : 0;
            int j = prec ? i - 1632 : i;
            int row = j >> 3, c16 = j & 7;
            int yyl = row / 34, xl = row - yyl * 34;
            int hh = h0 + yyl - 1, ww = xl - 1;
            uint4 v = make_uint4(0, 0, 0, 0);
            if ((unsigned)hh < 32u && (unsigned)ww < 32u) {
                size_t g = ((size_t)((b << 15) + (dp << 10) + (hh << 5) + ww) << 3) + c16;
                v = prec ? ((const uint4*)lo)[g] : ((const uint4*)hi)[g];
            }
            *(uint4*)(smem + prec * 26112 + row * 128 + ((c16 << 4) ^ ((row & 7) << 4))) = v;
        }
        for (int t9 = 0; t9 < 9; t9++) {
            int tap = dz * 9 + t9;
            __syncthreads();
            {   // stage W (pre-swizzled): 512 uint4 hi + 512 uint4 lo
                const uint4* wsh = (const uint4*)(wblob + (size_t)tap * 8192);
                const uint4* wsl = (const uint4*)(wblob + 221184 + (size_t)tap * 8192);
                uint4* wd = (uint4*)(smem + 52224);
                #pragma unroll
                for (int k = 0; k < 4; k++) {
                    wd[tid + (k << 7)] = wsh[tid + (k << 7)];
                    wd[512 + tid + (k << 7)] = wsl[tid + (k << 7)];
                }
            }
            __syncthreads();
            int dy = t9 / 3 - 1, dx = t9 - (t9 / 3) * 3 - 1;
            int srow_base = (wid + dy + 1) * 34 + (dx + 1);
            #pragma unroll
            for (int ks = 0; ks < 4; ks++) {
                uint32_t Ah[2][4], Al[2][4], Bh[8][2], Bl[8][2];
                int cb = (ks << 5) + a_cb;
                #pragma unroll
                for (int mt = 0; mt < 2; mt++) {
                    int row = srow_base + (mt << 4) + a_r;
                    uint32_t sw = (uint32_t)(cb ^ ((row & 7) << 4));
                    uint32_t addr = sb + (uint32_t)row * 128 + sw;
                    LDSM4(Ah[mt], addr);
                    LDSM4(Al[mt], addr + 26112);
                }
                {
                    int krow = (ks << 4) + (lane & 15);
                    uint32_t rbase = sb + 52224 + (uint32_t)krow * 128;
                    uint32_t xr = (uint32_t)((krow & 7) << 4);
                    int nbl = (lane >> 4) << 4;
                    #pragma unroll
                    for (int nt4 = 0; nt4 < 4; nt4++) {
                        uint32_t nb = (uint32_t)((nt4 << 5) + nbl);
                        uint32_t addr = rbase + (nb ^ xr);
                        LDSM4T(Bh[nt4*2][0], Bh[nt4*2][1], Bh[nt4*2+1][0], Bh[nt4*2+1][1], addr);
                        LDSM4T(Bl[nt4*2][0], Bl[nt4*2][1], Bl[nt4*2+1][0], Bl[nt4*2+1][1], addr + 8192);
                    }
                }
                #pragma unroll
                for (int mt = 0; mt < 2; mt++)
                    #pragma unroll
                    for (int nt = 0; nt < 8; nt++) {
                        MMA(acc[mt][nt], Ah[mt], Bh[nt]);
                        MMA(acc[mt][nt], Ah[mt], Bl[nt]);
                        MMA(acc[mt][nt], Al[mt], Bh[nt]);
                    }
            }
        }
    }
    // epilogue: write fp32 (b,v,c)
    int g = lane >> 2, tg = lane & 3;
    #pragma unroll
    for (int mt = 0; mt < 2; mt++) {
        int v0 = r0 + (wid << 5) + (mt << 4) + g;
        #pragma unroll
        for (int nt = 0; nt < 8; nt++) {
            int c = (nt << 3) + tg * 2;
            float* o = out + ((size_t)v0 << 6) + c;
            o[0] = acc[mt][nt][0];
            o[1] = acc[mt][nt][1];
            o[512] = acc[mt][nt][2];      // row +8 -> +8*64 floats
            o[513] = acc[mt][nt][3];
        }
    }
}

// ---------------- devox + fuse ----------------
__global__ void __launch_bounds__(128) k_devox(const float* __restrict__ coords,
                                               const float* __restrict__ wfuse) {
    __shared__ float swf[CC * CC];
    for (int i = threadIdx.x; i < CC * CC; i += 128) swf[(i & 63) * CC + (i >> 6)] = wfuse[i];
    __syncthreads();
    int p = blockIdx.x * 128 + threadIdx.x;
    int b = p >> 15, n = p & 32767;
    float cx = coords[p*3+0]*31.f, cy = coords[p*3+1]*31.f, cz = coords[p*3+2]*31.f;
    float fx = cx - floorf(cx), fy = cy - floorf(cy), fz = cz - floorf(cz);
    int x0 = min(max(__float2int_rd(cx),0),31), x1 = min(x0+1,31);
    int y0 = min(max(__float2int_rd(cy),0),31), y1 = min(y0+1,31);
    int z0 = min(max(__float2int_rd(cz),0),31), z1 = min(z0+1,31);
    const float4* base[8]; float wk[8]; int k = 0;
    #pragma unroll
    for (int ddx = 0; ddx < 2; ddx++)
        #pragma unroll
        for (int ddy = 0; ddy < 2; ddy++)
            #pragma unroll
            for (int ddz = 0; ddz < 2; ddz++) {
                int X = ddx?x1:x0, Y = ddy?y1:y0, Z = ddz?z1:z0;
                wk[k] = (ddx?fx:1.f-fx)*(ddy?fy:1.f-fy)*(ddz?fz:1.f-fz);
                base[k] = (const float4*)(g_vox_b + (((size_t)(b<<15) + ((X<<10)+(Y<<5)+Z)) << 6));
                k++;
            }
    float acc[CC];
    #pragma unroll
    for (int o = 0; o < CC; o++) acc[o] = 0.f;
    #pragma unroll
    for (int c4 = 0; c4 < 16; c4++) {
        float r[32];
        #pragma unroll
        for (int kk = 0; kk < 8; kk++) {
            float4 v = __ldg(base[kk] + c4);
            r[kk*4] = v.x; r[kk*4+1] = v.y; r[kk*4+2] = v.z; r[kk*4+3] = v.w;
        }
        #pragma unroll
        for (int j = 0; j < 4; j++) {
            float dd = r[j]*wk[0] + r[4+j]*wk[1] + r[8+j]*wk[2] + r[12+j]*wk[3]
                     + r[16+j]*wk[4] + r[20+j]*wk[5] + r[24+j]*wk[6] + r[28+j]*wk[7];
            const float4* wr = (const float4*)(swf + (c4*4+j)*CC);
            #pragma unroll
            for (int q = 0; q < 16; q++) {
                float4 ww = wr[q];
                acc[q*4+0] += dd*ww.x; acc[q*4+1] += dd*ww.y; acc[q*4+2] += dd*ww.z; acc[q*4+3] += dd*ww.w;
            }
        }
    }
    #pragma unroll
    for (int o = 0; o < CC; o++) g_pts[((b * CC + o) << 15) + n] = acc[o];
}

__global__ void __launch_bounds__(128) k_final(const float* __restrict__ f,
                                               const float* __restrict__ wskip,
                                               const float* __restrict__ gg,
                                               const float* __restrict__ gb,
                                               float* __restrict__ out) {
    __shared__ float sw[CIN * CC];
    __shared__ float sg[64], sb2[64];
    for (int i = threadIdx.x; i < CIN * CC; i += 128) sw[(i & 31) * CC + (i >> 5)] = wskip[i];
    if (threadIdx.x < 64) { sg[threadIdx.x] = gg[threadIdx.x]; sb2[threadIdx.x] = gb[threadIdx.x]; }
    __syncthreads();
    int p = blockIdx.x * 128 + threadIdx.x;
    int b = p >> 15, n = p & 32767;
    float acc[CC];
    #pragma unroll
    for (int o = 0; o < CC; o++) acc[o] = 0.f;
    for (int c = 0; c < CIN; c++) {
        float x = f[((b * CIN + c) << 15) + n];
        const float4* wr = (const float4*)(sw + c * CC);
        #pragma unroll
        for (int q = 0; q < 16; q++) {
            float4 ww = wr[q];
            acc[q*4+0] += x*ww.x; acc[q*4+1] += x*ww.y; acc[q*4+2] += x*ww.z; acc[q*4+3] += x*ww.w;
        }
    }
    #pragma unroll
    for (int o = 0; o < CC; o++) {
        int bg = b * NG + (o >> 3);
        float v = g_pts[((b * CC + o) << 15) + n];
        v = (v - g_mu[bg]) * g_rs[bg] * sg[o] + sb2[o];
        out[((b * CC + o) << 15) + n] = siluf(v) + acc[o];
    }
}

// ---------------------------------------------------------------------------
extern "C" void kernel_launch(void* const* d_in, const int* in_sizes, int n_in,
                              void* d_out, int out_size) {
    const float* feats  = (const float*)d_in[0];
    const float* coords = (const float*)d_in[1];
    const float* t_emb  = (const float*)d_in[2];
    const float* w_in   = (const float*)d_in[3];
    const float* gn1_g  = (const float*)d_in[4];
    const float* gn1_b  = (const float*)d_in[5];
    const float* w_time = (const float*)d_in[6];
    const float* b_time = (const float*)d_in[7];
    const float* w_vox1 = (const float*)d_in[8];
    const float* gn2_g  = (const float*)d_in[9];
    const float* gn2_b  = (const float*)d_in[10];
    const float* w_vox2 = (const float*)d_in[11];
    const float* gn3_g  = (const float*)d_in[12];
    const float* gn3_b  = (const float*)d_in[13];
    const float* w_fuse = (const float*)d_in[14];
    const float* gn4_g  = (const float*)d_in[15];
    const float* gn4_b  = (const float*)d_in[16];
    const float* w_skip = (const float*)d_in[17];
    float* out = (float*)d_out;

    float *pts, *va, *vb;
    __half *hp, *lp;
    unsigned char* wb;
    cudaGetSymbolAddress((void**)&pts, g_pts);
    cudaGetSymbolAddress((void**)&va, g_vox_a);
    cudaGetSymbolAddress((void**)&vb, g_vox_b);
    cudaGetSymbolAddress((void**)&hp, g_hi);
    cudaGetSymbolAddress((void**)&lp, g_lo);
    cudaGetSymbolAddress((void**)&wb, g_wblob);

    static int attr_set = 0;
    if (!attr_set) {
        cudaFuncSetAttribute(k_conv_mma, cudaFuncAttributeMaxDynamicSharedMemorySize, CONV_SMEM);
        attr_set = 1;
    }

    k_bias<<<NB, 64>>>(t_emb, w_time, b_time);
    k_wprep<<<864, 256>>>(w_vox1, w_vox2);
    k_pw_in<<<1024, 128>>>(feats, w_in);
    k_st1<<<1024, 256>>>(pts);  k_st2<<<1, 32>>>();
    k_zero<<<2048, 256>>>();
    k_scatter<<<1024, 128>>>(coords, gn1_g, gn1_b);
    k_voxfin_cvt<<<512, 256>>>();
    k_conv_mma<<<1024, 128, CONV_SMEM>>>(hp, lp, wb, va);
    k_st1_vc<<<1024, 256>>>(va);  k_st2<<<1, 32>>>();
    k_gnsilu_cvt<<<512, 256>>>(va, gn2_g, gn2_b);
    k_conv_mma<<<1024, 128, CONV_SMEM>>>(hp, lp, wb + 442368, vb);
    k_st1_vc<<<1024, 256>>>(vb);  k_st2<<<1, 32>>>();
    k_gnsilu_vc<<<512, 256>>>(vb, gn3_g, gn3_b);
    k_devox<<<1024, 128>>>(coords, w_fuse);
    k_st1<<<1024, 256>>>(pts);  k_st2<<<1, 32>>>();
    k_final<<<1024, 128>>>(feats, w_skip, gn4_g, gn4_b, out);
}

// round 7
// speedup vs baseline: 1.2588x; 1.0746x over previous
#include <cuda_runtime.h>
#include <cuda_fp16.h>
#include <cstdint>

#define NB   4
#define CIN  32
#define CC   64
#define V3   32768
#define NG   8
#define EPS  1e-5f

__device__ __align__(16) float g_pts[NB * CC * V3];
__device__ __align__(16) float g_vox_a[NB * V3 * CC];
__device__ __align__(16) float g_vox_b[NB * V3 * CC];
__device__ __align__(16) __half g_hi[NB * V3 * CC];
__device__ __align__(16) __half g_lo[NB * V3 * CC];
__device__ __align__(16) unsigned char g_wblob[884736];  // [conv][prec][tap][64x128B sw128]
__device__ int   g_cnt[NB * V3];
__device__ float g_bias[NB * CC];
__device__ float g_mu[NB * NG];
__device__ float g_rs[NB * NG];
__device__ float g_ps[1024];
__device__ float g_pq[1024];

__device__ __forceinline__ float siluf(float x) { return x / (1.f + __expf(-x)); }

__device__ __forceinline__ uint32_t s2u(const void* p) {
    uint32_t a;
    asm("{ .reg .u64 t; cvta.to.shared.u64 t, %1; cvt.u32.u64 %0, t; }" : "=r"(a) : "l"(p));
    return a;
}

#define LDSM4(R, addr) \
    asm volatile("ldmatrix.sync.aligned.m8n8.x4.shared.b16 {%0,%1,%2,%3}, [%4];" \
        : "=r"((R)[0]), "=r"((R)[1]), "=r"((R)[2]), "=r"((R)[3]) : "r"(addr))
#define LDSM4T(r0, r1, r2, r3, addr) \
    asm volatile("ldmatrix.sync.aligned.m8n8.x4.trans.shared.b16 {%0,%1,%2,%3}, [%4];" \
        : "=r"(r0), "=r"(r1), "=r"(r2), "=r"(r3) : "r"(addr))
#define MMA(dacc, A, B) \
    asm volatile("mma.sync.aligned.m16n8k16.row.col.f32.f16.f16.f32 " \
        "{%0,%1,%2,%3}, {%4,%5,%6,%7}, {%8,%9}, {%0,%1,%2,%3};" \
        : "+f"((dacc)[0]), "+f"((dacc)[1]), "+f"((dacc)[2]), "+f"((dacc)[3]) \
        : "r"((A)[0]), "r"((A)[1]), "r"((A)[2]), "r"((A)[3]), "r"((B)[0]), "r"((B)[1]))

__device__ __forceinline__ void cp16(uint32_t dst, const void* src) {
    asm volatile("cp.async.cg.shared.global [%0], [%1], 16;" :: "r"(dst), "l"(src));
}
__device__ __forceinline__ void cp16z(uint32_t dst, const void* src, bool ok) {
    int sz = ok ? 16 : 0;
    asm volatile("cp.async.cg.shared.global [%0], [%1], 16, %2;" :: "r"(dst), "l"(src), "r"(sz));
}
#define CP_COMMIT() asm volatile("cp.async.commit_group;" ::: "memory")
#define CP_WAIT(n)  asm volatile("cp.async.wait_group %0;" :: "n"(n) : "memory")

__device__ __forceinline__ void hi_lo(float v, unsigned short& h, unsigned short& l) {
    __half hb = __float2half_rn(v);
    h = __half_as_ushort(hb);
    l = __half_as_ushort(__float2half_rn(v - __half2float(hb)));
}

// ---------------- small kernels ----------------
__global__ void k_bias(const float* __restrict__ te_, const float* __restrict__ wt,
                       const float* __restrict__ bt) {
    __shared__ float te[256];
    int b = blockIdx.x, o = threadIdx.x;
    for (int i = o; i < 256; i += 64) te[i] = te_[b * 256 + i];
    __syncthreads();
    float s = bt[o];
    #pragma unroll 8
    for (int t = 0; t < 256; t++) s += te[t] * wt[o * 256 + t];
    g_bias[b * CC + o] = s;
}

__global__ void __launch_bounds__(128) k_pw_in(const float* __restrict__ f, const float* __restrict__ w) {
    __shared__ float sw[CIN * CC];
    for (int i = threadIdx.x; i < CIN * CC; i += 128) sw[(i & 31) * CC + (i >> 5)] = w[i];
    __syncthreads();
    int p = blockIdx.x * 128 + threadIdx.x;
    int b = p >> 15, n = p & 32767;
    float acc[CC];
    #pragma unroll
    for (int o = 0; o < CC; o++) acc[o] = 0.f;
    for (int c = 0; c < CIN; c++) {
        float x = f[((b * CIN + c) << 15) + n];
        const float4* wr = (const float4*)(sw + c * CC);
        #pragma unroll
        for (int q = 0; q < 16; q++) {
            float4 ww = wr[q];
            acc[q*4+0] += x*ww.x; acc[q*4+1] += x*ww.y; acc[q*4+2] += x*ww.z; acc[q*4+3] += x*ww.w;
        }
    }
    #pragma unroll
    for (int o = 0; o < CC; o++) g_pts[((b * CC + o) << 15) + n] = acc[o];
}

// ---- two-stage GN stats ----
__global__ void __launch_bounds__(256) k_st1(const float* __restrict__ buf) {   // (b,c,n)
    __shared__ float ss[256], sq2[256];
    int bg = blockIdx.x >> 5, ch = blockIdx.x & 31;
    const float4* p = (const float4*)(buf + (size_t)bg * 262144 + ch * 8192);
    float s = 0.f, q = 0.f;
    for (int i = threadIdx.x; i < 2048; i += 256) {
        float4 v = p[i];
        s += v.x + v.y + v.z + v.w;
        q += v.x*v.x + v.y*v.y + v.z*v.z + v.w*v.w;
    }
    ss[threadIdx.x] = s; sq2[threadIdx.x] = q; __syncthreads();
    for (int st = 128; st > 0; st >>= 1) {
        if (threadIdx.x < st) { ss[threadIdx.x] += ss[threadIdx.x+st]; sq2[threadIdx.x] += sq2[threadIdx.x+st]; }
        __syncthreads();
    }
    if (threadIdx.x == 0) { g_ps[blockIdx.x] = ss[0]; g_pq[blockIdx.x] = sq2[0]; }
}

__global__ void __launch_bounds__(256) k_st1_vc(const float* __restrict__ buf) {  // (b,v,c)
    __shared__ float ss[256], sq2[256];
    int bg = blockIdx.x >> 5, ch = blockIdx.x & 31;
    int b = bg >> 3, g = bg & 7;
    const float4* base = (const float4*)(buf + ((size_t)b << 21) + (g << 3));
    float s = 0.f, q = 0.f;
    for (int i = threadIdx.x; i < 2048; i += 256) {
        int v = (ch << 10) + (i >> 1);
        float4 x = base[(size_t)v * 16 + (i & 1)];
        s += x.x + x.y + x.z + x.w;
        q += x.x*x.x + x.y*x.y + x.z*x.z + x.w*x.w;
    }
    ss[threadIdx.x] = s; sq2[threadIdx.x] = q; __syncthreads();
    for (int st = 128; st > 0; st >>= 1) {
        if (threadIdx.x < st) { ss[threadIdx.x] += ss[threadIdx.x+st]; sq2[threadIdx.x] += sq2[threadIdx.x+st]; }
        __syncthreads();
    }
    if (threadIdx.x == 0) { g_ps[blockIdx.x] = ss[0]; g_pq[blockIdx.x] = sq2[0]; }
}

__global__ void k_st2() {
    int bg = threadIdx.x;
    if (bg < 32) {
        float s = 0.f, q = 0.f;
        #pragma unroll
        for (int c = 0; c < 32; c++) { s += g_ps[bg * 32 + c]; q += g_pq[bg * 32 + c]; }
        float m = s * (1.f / 262144.f);
        float v = q * (1.f / 262144.f) - m * m;
        g_mu[bg] = m; g_rs[bg] = rsqrtf(v + EPS);
    }
}

__global__ void k_zero() {
    int t = blockIdx.x * 256 + threadIdx.x;           // 524288 threads, 4 float4 each
    float4 z = make_float4(0.f, 0.f, 0.f, 0.f);
    float4* p = (float4*)g_vox_a;
    p[t] = z; p[t + 524288] = z; p[t + 1048576] = z; p[t + 1572864] = z;
    if (t < 32768) ((int4*)g_cnt)[t] = make_int4(0, 0, 0, 0);
}

__global__ void __launch_bounds__(128) k_scatter(const float* __restrict__ coords,
                                                 const float* __restrict__ gg,
                                                 const float* __restrict__ gb) {
    int p = blockIdx.x * 128 + threadIdx.x;
    int b = p >> 15, n = p & 32767;
    int ix = min(max(__float2int_rd(coords[p*3+0]*31.f), 0), 31);
    int iy = min(max(__float2int_rd(coords[p*3+1]*31.f), 0), 31);
    int iz = min(max(__float2int_rd(coords[p*3+2]*31.f), 0), 31);
    int flat = (ix << 10) + (iy << 5) + iz;
    atomicAdd(&g_cnt[(b << 15) + flat], 1);
    float* dst = g_vox_a + ((size_t)((b << 15) + flat) << 6);
    #pragma unroll 4
    for (int c = 0; c < CC; c++) {
        int bg = b * NG + (c >> 3);
        float x = g_pts[((b * CC + c) << 15) + n];
        x = siluf((x - g_mu[bg]) * g_rs[bg] * gg[c] + gb[c]) + g_bias[b * CC + c];
        atomicAdd(dst + c, x);
    }
}

__global__ void k_voxfin_cvt() {
    int idx = blockIdx.x * 256 + threadIdx.x;           // b*V3+v
    int b = idx >> 15;
    float inv = 1.f / (float)max(g_cnt[idx], 1);
    const float4* s4 = (const float4*)(g_vox_a + ((size_t)idx << 6));
    uint4* h4 = (uint4*)(g_hi + ((size_t)idx << 6));
    uint4* l4 = (uint4*)(g_lo + ((size_t)idx << 6));
    const float* bias = g_bias + b * CC;
    #pragma unroll
    for (int q = 0; q < 8; q++) {
        float4 v0 = s4[q*2], v1 = s4[q*2+1];
        float x[8] = {v0.x,v0.y,v0.z,v0.w,v1.x,v1.y,v1.z,v1.w};
        unsigned short hs[8], ls[8];
        #pragma unroll
        for (int j = 0; j < 8; j++) hi_lo(x[j]*inv + bias[q*8+j], hs[j], ls[j]);
        h4[q] = make_uint4(hs[0]|((uint32_t)hs[1]<<16), hs[2]|((uint32_t)hs[3]<<16),
                           hs[4]|((uint32_t)hs[5]<<16), hs[6]|((uint32_t)hs[7]<<16));
        l4[q] = make_uint4(ls[0]|((uint32_t)ls[1]<<16), ls[2]|((uint32_t)ls[3]<<16),
                           ls[4]|((uint32_t)ls[5]<<16), ls[6]|((uint32_t)ls[7]<<16));
    }
}

__global__ void k_gnsilu_cvt(const float* __restrict__ src,
                             const float* __restrict__ gg, const float* __restrict__ gb) {
    int idx = blockIdx.x * 256 + threadIdx.x;
    int b = idx >> 15;
    const float4* s4 = (const float4*)(src + ((size_t)idx << 6));
    uint4* h4 = (uint4*)(g_hi + ((size_t)idx << 6));
    uint4* l4 = (uint4*)(g_lo + ((size_t)idx << 6));
    #pragma unroll
    for (int q = 0; q < 8; q++) {
        float mu = g_mu[b*NG+q], rs = g_rs[b*NG+q];
        float4 v0 = s4[q*2], v1 = s4[q*2+1];
        float x[8] = {v0.x,v0.y,v0.z,v0.w,v1.x,v1.y,v1.z,v1.w};
        unsigned short hs[8], ls[8];
        #pragma unroll
        for (int j = 0; j < 8; j++) {
            int c = q*8+j;
            hi_lo(siluf((x[j]-mu)*rs*gg[c] + gb[c]), hs[j], ls[j]);
        }
        h4[q] = make_uint4(hs[0]|((uint32_t)hs[1]<<16), hs[2]|((uint32_t)hs[3]<<16),
                           hs[4]|((uint32_t)hs[5]<<16), hs[6]|((uint32_t)hs[7]<<16));
        l4[q] = make_uint4(ls[0]|((uint32_t)ls[1]<<16), ls[2]|((uint32_t)ls[3]<<16),
                           ls[4]|((uint32_t)ls[5]<<16), ls[6]|((uint32_t)ls[7]<<16));
    }
}

__global__ void k_gnsilu_vc(float* __restrict__ buf,
                            const float* __restrict__ gg, const float* __restrict__ gb) {
    int idx = blockIdx.x * 256 + threadIdx.x;
    int b = idx >> 15;
    float4* s4 = (float4*)(buf + ((size_t)idx << 6));
    #pragma unroll
    for (int q = 0; q < 8; q++) {
        float mu = g_mu[b*NG+q], rs = g_rs[b*NG+q];
        float4 v0 = s4[q*2], v1 = s4[q*2+1];
        float x[8] = {v0.x,v0.y,v0.z,v0.w,v1.x,v1.y,v1.z,v1.w};
        #pragma unroll
        for (int j = 0; j < 8; j++) {
            int c = q*8+j;
            x[j] = siluf((x[j]-mu)*rs*gg[c] + gb[c]);
        }
        s4[q*2]   = make_float4(x[0],x[1],x[2],x[3]);
        s4[q*2+1] = make_float4(x[4],x[5],x[6],x[7]);
    }
}

// wblob: B matrix per tap: row k = c_in (64 rows x 128B), col n = o_out, SW128 swizzled.
__global__ void k_wprep(const float* __restrict__ w1, const float* __restrict__ w2) {
    int i = blockIdx.x * 256 + threadIdx.x;
    if (i >= 221184) return;
    int conv = i / 110592, r = i - conv * 110592;
    int o = r / 1728, r2 = r - o * 1728;
    int c = r2 / 27, t = r2 - c * 27;
    float w = conv ? w2[r] : w1[r];
    __half h = __float2half_rn(w);
    __half l = __float2half_rn(w - __half2float(h));
    uint32_t off = (uint32_t)c * 128 + (uint32_t)o * 2;
    uint32_t swo = off ^ ((off >> 3) & 0x70);
    size_t base = (size_t)conv * 442368;
    *(__half*)(g_wblob + base + (size_t)t * 8192 + swo) = h;
    *(__half*)(g_wblob + base + 221184 + (size_t)t * 8192 + swo) = l;
}

// ---------------- HMMA conv: cp.async pipelined, 256 thr, 3 W buffers ----------------
// smem: A hi [0, 26112) = 204 rows(6y x 34x) x 128B; A lo [26112, 52224);
//       W slots [52224 + s*16384): hi 8KB | lo 8KB, s = 0..2
#define CONV_SMEM 101376

__global__ void __launch_bounds__(256, 2)
k_conv_mma(const __half* __restrict__ hi, const __half* __restrict__ lo,
           const unsigned char* __restrict__ wblob, float* __restrict__ out) {
    extern __shared__ char smem[];
    const uint32_t sb = s2u(smem);
    const int tid = threadIdx.x, wid = tid >> 5, lane = tid & 31;
    int t = blockIdx.x;                     // b*256 + d*8 + hg
    int b = t >> 8, tt = t & 255;
    int d = tt >> 3, h0 = (tt & 7) << 2;
    int r0 = t << 7;                        // base output voxel index (b,v)

    int dzlist[3]; int ndz = 0;
    #pragma unroll
    for (int dz = 0; dz < 3; dz++) { int dp = d + dz - 1; if ((unsigned)dp < 32u) dzlist[ndz++] = dz; }
    int ntaps = ndz * 9;

    float acc[8][4];
    #pragma unroll
    for (int nt = 0; nt < 8; nt++)
        #pragma unroll
        for (int k = 0; k < 4; k++) acc[nt][k] = 0.f;

    const int a_r  = lane & 15;
    const int a_cb = (lane >> 4) << 4;

    // ---- W prefetch: tap sequence index i -> slot i%3 ----
    auto stage_w = [&](int i) {
        int tap = dzlist[i / 9] * 9 + (i % 9);
        const unsigned char* wh = wblob + (size_t)tap * 8192;
        const unsigned char* wl = wblob + 221184 + (size_t)tap * 8192;
        uint32_t dst = sb + 52224 + (uint32_t)(i % 3) * 16384;
        int j0 = tid << 4, j1 = (tid + 256) << 4;
        cp16(dst + j0, wh + j0);           // hi: 512 x 16B
        cp16(dst + j1, wh + j1);
        cp16(dst + 8192 + j0, wl + j0);    // lo
        cp16(dst + 8192 + j1, wl + j1);
    };

    stage_w(0); CP_COMMIT();

    for (int s = 0; s < ndz; s++) {
        int dp = d + dzlist[s] - 1;
        __syncthreads();                   // prev slab MMAs done before A overwrite
        // stage A slab via cp.async (zfill OOB): rows = yy*34 + (x+1), yy 0..5, x -1..32
        for (int i = tid; i < 1632; i += 256) {
            int row = i >> 3, c16 = i & 7;
            int yyl = row / 34, xl = row - yyl * 34;
            int hh = h0 + yyl - 1, ww = xl - 1;
            bool ok = ((unsigned)hh < 32u) && ((unsigned)ww < 32u);
            size_t g = ok ? (((size_t)((b << 15) + (dp << 10) + (hh << 5) + ww) << 3) + c16) : 0;
            uint32_t doff = (uint32_t)row * 128 + ((c16 << 4) ^ ((row & 7) << 4));
            cp16z(sb + doff,         (const uint4*)hi + g, ok);
            cp16z(sb + 26112 + doff, (const uint4*)lo + g, ok);
        }
        CP_COMMIT();
        for (int t9 = 0; t9 < 9; t9++) {
            int i = s * 9 + t9;
            if (i + 1 < ntaps) stage_w(i + 1);
            CP_COMMIT();
            CP_WAIT(1);                    // A(s) + W(i) complete; W(i+1) may fly
            __syncthreads();
            uint32_t wbase = sb + 52224 + (uint32_t)(i % 3) * 16384;
            int dy = t9 / 3 - 1, dx = t9 - (t9 / 3) * 3 - 1;
            int srow_base = ((wid >> 1) + dy + 1) * 34 + ((wid & 1) << 4) + dx + 1;
            #pragma unroll
            for (int ks = 0; ks < 4; ks++) {
                uint32_t Ah[4], Al[4], Bh[8][2], Bl[8][2];
                {
                    int row = srow_base + a_r;
                    uint32_t sw = (uint32_t)(((ks << 5) + a_cb) ^ ((row & 7) << 4));
                    uint32_t addr = sb + (uint32_t)row * 128 + sw;
                    LDSM4(Ah, addr);
                    LDSM4(Al, addr + 26112);
                }
                {
                    int krow = (ks << 4) + (lane & 15);
                    uint32_t rbase = wbase + (uint32_t)krow * 128;
                    uint32_t xr = (uint32_t)((krow & 7) << 4);
                    int nbl = (lane >> 4) << 4;
                    #pragma unroll
                    for (int nt4 = 0; nt4 < 4; nt4++) {
                        uint32_t nb = (uint32_t)((nt4 << 5) + nbl);
                        uint32_t addr = rbase + (nb ^ xr);
                        LDSM4T(Bh[nt4*2][0], Bh[nt4*2][1], Bh[nt4*2+1][0], Bh[nt4*2+1][1], addr);
                        LDSM4T(Bl[nt4*2][0], Bl[nt4*2][1], Bl[nt4*2+1][0], Bl[nt4*2+1][1], addr + 8192);
                    }
                }
                #pragma unroll
                for (int nt = 0; nt < 8; nt++) {
                    MMA(acc[nt], Ah, Bh[nt]);
                    MMA(acc[nt], Ah, Bl[nt]);
                    MMA(acc[nt], Al, Bh[nt]);
                }
            }
        }
    }
    // epilogue: write fp32 (b,v,c); warp owns 16 voxels
    int g = lane >> 2, tg = lane & 3;
    int v0 = r0 + (wid << 4) + g;
    #pragma unroll
    for (int nt = 0; nt < 8; nt++) {
        int c = (nt << 3) + tg * 2;
        float* o = out + ((size_t)v0 << 6) + c;
        o[0] = acc[nt][0];
        o[1] = acc[nt][1];
        o[512] = acc[nt][2];      // row +8 -> +8*64 floats
        o[513] = acc[nt][3];
    }
}

// ---------------- devox + fuse ----------------
__global__ void __launch_bounds__(128) k_devox(const float* __restrict__ coords,
                                               const float* __restrict__ wfuse) {
    __shared__ float swf[CC * CC];
    for (int i = threadIdx.x; i < CC * CC; i += 128) swf[(i & 63) * CC + (i >> 6)] = wfuse[i];
    __syncthreads();
    int p = blockIdx.x * 128 + threadIdx.x;
    int b = p >> 15, n = p & 32767;
    float cx = coords[p*3+0]*31.f, cy = coords[p*3+1]*31.f, cz = coords[p*3+2]*31.f;
    float fx = cx - floorf(cx), fy = cy - floorf(cy), fz = cz - floorf(cz);
    int x0 = min(max(__float2int_rd(cx),0),31), x1 = min(x0+1,31);
    int y0 = min(max(__float2int_rd(cy),0),31), y1 = min(y0+1,31);
    int z0 = min(max(__float2int_rd(cz),0),31), z1 = min(z0+1,31);
    const float4* base[8]; float wk[8]; int k = 0;
    #pragma unroll
    for (int ddx = 0; ddx < 2; ddx++)
        #pragma unroll
        for (int ddy = 0; ddy < 2; ddy++)
            #pragma unroll
            for (int ddz = 0; ddz < 2; ddz++) {
                int X = ddx?x1:x0, Y = ddy?y1:y0, Z = ddz?z1:z0;
                wk[k] = (ddx?fx:1.f-fx)*(ddy?fy:1.f-fy)*(ddz?fz:1.f-fz);
                base[k] = (const float4*)(g_vox_b + (((size_t)(b<<15) + ((X<<10)+(Y<<5)+Z)) << 6));
                k++;
            }
    float acc[CC];
    #pragma unroll
    for (int o = 0; o < CC; o++) acc[o] = 0.f;
    #pragma unroll
    for (int c4 = 0; c4 < 16; c4++) {
        float r[32];
        #pragma unroll
        for (int kk = 0; kk < 8; kk++) {
            float4 v = __ldg(base[kk] + c4);
            r[kk*4] = v.x; r[kk*4+1] = v.y; r[kk*4+2] = v.z; r[kk*4+3] = v.w;
        }
        #pragma unroll
        for (int j = 0; j < 4; j++) {
            float dd = r[j]*wk[0] + r[4+j]*wk[1] + r[8+j]*wk[2] + r[12+j]*wk[3]
                     + r[16+j]*wk[4] + r[20+j]*wk[5] + r[24+j]*wk[6] + r[28+j]*wk[7];
            const float4* wr = (const float4*)(swf + (c4*4+j)*CC);
            #pragma unroll
            for (int q = 0; q < 16; q++) {
                float4 ww = wr[q];
                acc[q*4+0] += dd*ww.x; acc[q*4+1] += dd*ww.y; acc[q*4+2] += dd*ww.z; acc[q*4+3] += dd*ww.w;
            }
        }
    }
    #pragma unroll
    for (int o = 0; o < CC; o++) g_pts[((b * CC + o) << 15) + n] = acc[o];
}

__global__ void __launch_bounds__(128) k_final(const float* __restrict__ f,
                                               const float* __restrict__ wskip,
                                               const float* __restrict__ gg,
                                               const float* __restrict__ gb,
                                               float* __restrict__ out) {
    __shared__ float sw[CIN * CC];
    __shared__ float sg[64], sb2[64];
    for (int i = threadIdx.x; i < CIN * CC; i += 128) sw[(i & 31) * CC + (i >> 5)] = wskip[i];
    if (threadIdx.x < 64) { sg[threadIdx.x] = gg[threadIdx.x]; sb2[threadIdx.x] = gb[threadIdx.x]; }
    __syncthreads();
    int p = blockIdx.x * 128 + threadIdx.x;
    int b = p >> 15, n = p & 32767;
    float acc[CC];
    #pragma unroll
    for (int o = 0; o < CC; o++) acc[o] = 0.f;
    for (int c = 0; c < CIN; c++) {
        float x = f[((b * CIN + c) << 15) + n];
        const float4* wr = (const float4*)(sw + c * CC);
        #pragma unroll
        for (int q = 0; q < 16; q++) {
            float4 ww = wr[q];
            acc[q*4+0] += x*ww.x; acc[q*4+1] += x*ww.y; acc[q*4+2] += x*ww.z; acc[q*4+3] += x*ww.w;
        }
    }
    #pragma unroll
    for (int o = 0; o < CC; o++) {
        int bg = b * NG + (o >> 3);
        float v = g_pts[((b * CC + o) << 15) + n];
        v = (v - g_mu[bg]) * g_rs[bg] * sg[o] + sb2[o];
        out[((b * CC + o) << 15) + n] = siluf(v) + acc[o];
    }
}

// ---------------------------------------------------------------------------
extern "C" void kernel_launch(void* const* d_in, const int* in_sizes, int n_in,
                              void* d_out, int out_size) {
    const float* feats  = (const float*)d_in[0];
    const float* coords = (const float*)d_in[1];
    const float* t_emb  = (const float*)d_in[2];
    const float* w_in   = (const float*)d_in[3];
    const float* gn1_g  = (const float*)d_in[4];
    const float* gn1_b  = (const float*)d_in[5];
    const float* w_time = (const float*)d_in[6];
    const float* b_time = (const float*)d_in[7];
    const float* w_vox1 = (const float*)d_in[8];
    const float* gn2_g  = (const float*)d_in[9];
    const float* gn2_b  = (const float*)d_in[10];
    const float* w_vox2 = (const float*)d_in[11];
    const float* gn3_g  = (const float*)d_in[12];
    const float* gn3_b  = (const float*)d_in[13];
    const float* w_fuse = (const float*)d_in[14];
    const float* gn4_g  = (const float*)d_in[15];
    const float* gn4_b  = (const float*)d_in[16];
    const float* w_skip = (const float*)d_in[17];
    float* out = (float*)d_out;

    float *pts, *va, *vb;
    __half *hp, *lp;
    unsigned char* wb;
    cudaGetSymbolAddress((void**)&pts, g_pts);
    cudaGetSymbolAddress((void**)&va, g_vox_a);
    cudaGetSymbolAddress((void**)&vb, g_vox_b);
    cudaGetSymbolAddress((void**)&hp, g_hi);
    cudaGetSymbolAddress((void**)&lp, g_lo);
    cudaGetSymbolAddress((void**)&wb, g_wblob);

    static int attr_set = 0;
    if (!attr_set) {
        cudaFuncSetAttribute(k_conv_mma, cudaFuncAttributeMaxDynamicSharedMemorySize, CONV_SMEM);
        attr_set = 1;
    }

    k_zero<<<2048, 256>>>();
    k_bias<<<NB, 64>>>(t_emb, w_time, b_time);
    k_wprep<<<864, 256>>>(w_vox1, w_vox2);
    k_pw_in<<<1024, 128>>>(feats, w_in);
    k_st1<<<1024, 256>>>(pts);  k_st2<<<1, 32>>>();
    k_scatter<<<1024, 128>>>(coords, gn1_g, gn1_b);
    k_voxfin_cvt<<<512, 256>>>();
    k_conv_mma<<<1024, 256, CONV_SMEM>>>(hp, lp, wb, va);
    k_st1_vc<<<1024, 256>>>(va);  k_st2<<<1, 32>>>();
    k_gnsilu_cvt<<<512, 256>>>(va, gn2_g, gn2_b);
    k_conv_mma<<<1024, 256, CONV_SMEM>>>(hp, lp, wb + 442368, vb);
    k_st1_vc<<<1024, 256>>>(vb);  k_st2<<<1, 32>>>();
    k_gnsilu_vc<<<512, 256>>>(vb, gn3_g, gn3_b);
    k_devox<<<1024, 128>>>(coords, w_fuse);
    k_st1<<<1024, 256>>>(pts);  k_st2<<<1, 32>>>();
    k_final<<<1024, 128>>>(feats, w_skip, gn4_g, gn4_b, out);
}

// round 8
// speedup vs baseline: 1.2762x; 1.0138x over previous
#include <cuda_runtime.h>
#include <cuda_fp16.h>
#include <cstdint>

#define NB   4
#define CIN  32
#define CC   64
#define V3   32768
#define NG   8
#define EPS  1e-5f

__device__ __align__(16) float g_pts[NB * CC * V3];
__device__ __align__(16) float g_vox_a[NB * V3 * CC];
__device__ __align__(16) float g_vox_b[NB * V3 * CC];
__device__ __align__(16) __half g_hi[NB * V3 * CC];
__device__ __align__(16) __half g_lo[NB * V3 * CC];
__device__ __align__(16) unsigned char g_wblob[884736];  // [conv][prec][tap][64x128B sw128]
__device__ int   g_cnt[NB * V3];
__device__ float g_bias[NB * CC];
__device__ float g_mu[NB * NG];
__device__ float g_rs[NB * NG];
__device__ float g_sac[128];   // 4 passes x 32 (b,g) sums
__device__ float g_qac[128];   // sumsq

__device__ __forceinline__ float siluf(float x) { return x / (1.f + __expf(-x)); }

__device__ __forceinline__ uint32_t s2u(const void* p) {
    uint32_t a;
    asm("{ .reg .u64 t; cvta.to.shared.u64 t, %1; cvt.u32.u64 %0, t; }" : "=r"(a) : "l"(p));
    return a;
}

#define LDSM4(R, addr) \
    asm volatile("ldmatrix.sync.aligned.m8n8.x4.shared.b16 {%0,%1,%2,%3}, [%4];" \
        : "=r"((R)[0]), "=r"((R)[1]), "=r"((R)[2]), "=r"((R)[3]) : "r"(addr))
#define LDSM4T(r0, r1, r2, r3, addr) \
    asm volatile("ldmatrix.sync.aligned.m8n8.x4.trans.shared.b16 {%0,%1,%2,%3}, [%4];" \
        : "=r"(r0), "=r"(r1), "=r"(r2), "=r"(r3) : "r"(addr))
#define MMA(dacc, A, B) \
    asm volatile("mma.sync.aligned.m16n8k16.row.col.f32.f16.f16.f32 " \
        "{%0,%1,%2,%3}, {%4,%5,%6,%7}, {%8,%9}, {%0,%1,%2,%3};" \
        : "+f"((dacc)[0]), "+f"((dacc)[1]), "+f"((dacc)[2]), "+f"((dacc)[3]) \
        : "r"((A)[0]), "r"((A)[1]), "r"((A)[2]), "r"((A)[3]), "r"((B)[0]), "r"((B)[1]))

__device__ __forceinline__ void cp16(uint32_t dst, const void* src) {
    asm volatile("cp.async.cg.shared.global [%0], [%1], 16;" :: "r"(dst), "l"(src));
}
__device__ __forceinline__ void cp16z(uint32_t dst, const void* src, bool ok) {
    int sz = ok ? 16 : 0;
    asm volatile("cp.async.cg.shared.global [%0], [%1], 16, %2;" :: "r"(dst), "l"(src), "r"(sz));
}
#define CP_COMMIT() asm volatile("cp.async.commit_group;" ::: "memory")
#define CP_WAIT(n)  asm volatile("cp.async.wait_group %0;" :: "n"(n) : "memory")

__device__ __forceinline__ void hi_lo(float v, unsigned short& h, unsigned short& l) {
    __half hb = __float2half_rn(v);
    h = __half_as_ushort(hb);
    l = __half_as_ushort(__float2half_rn(v - __half2float(hb)));
}

// ---------------- small kernels ----------------
__global__ void k_bias(const float* __restrict__ te_, const float* __restrict__ wt,
                       const float* __restrict__ bt) {
    __shared__ float te[256];
    int b = blockIdx.x, o = threadIdx.x;
    for (int i = o; i < 256; i += 64) te[i] = te_[b * 256 + i];
    __syncthreads();
    float s = bt[o];
    #pragma unroll 8
    for (int t = 0; t < 256; t++) s += te[t] * wt[o * 256 + t];
    g_bias[b * CC + o] = s;
}

// pw_in: 256 thr, 2 threads/point (32 out-ch each), fused GN1 stats (pass 0)
__global__ void __launch_bounds__(256) k_pw_in(const float* __restrict__ f,
                                               const float* __restrict__ w,
                                               float* __restrict__ sac, float* __restrict__ qac) {
    __shared__ float sw[CIN * CC];
    __shared__ float rsm[8][4], rqm[8][4];
    int tid = threadIdx.x;
    for (int i = tid; i < CIN * CC; i += 256) sw[(i & 31) * CC + (i >> 5)] = w[i];
    __syncthreads();
    int half = tid >> 7;
    int p = blockIdx.x * 128 + (tid & 127);
    int b = p >> 15, n = p & 32767;
    int o0 = half << 5;
    float acc[32];
    #pragma unroll
    for (int o = 0; o < 32; o++) acc[o] = 0.f;
    for (int c = 0; c < CIN; c++) {
        float x = f[((b * CIN + c) << 15) + n];
        const float4* wr = (const float4*)(sw + c * CC + o0);
        #pragma unroll
        for (int q = 0; q < 8; q++) {
            float4 ww = wr[q];
            acc[q*4+0] += x*ww.x; acc[q*4+1] += x*ww.y; acc[q*4+2] += x*ww.z; acc[q*4+3] += x*ww.w;
        }
    }
    #pragma unroll
    for (int o = 0; o < 32; o++) g_pts[((b * CC + o0 + o) << 15) + n] = acc[o];
    // fused stats: this thread covers groups half*4 .. half*4+3
    float s4[4], q4[4];
    #pragma unroll
    for (int g = 0; g < 4; g++) {
        float s = 0.f, q = 0.f;
        #pragma unroll
        for (int j = 0; j < 8; j++) { float v = acc[g*8+j]; s += v; q += v*v; }
        s4[g] = s; q4[g] = q;
    }
    #pragma unroll
    for (int off = 16; off > 0; off >>= 1)
        #pragma unroll
        for (int g = 0; g < 4; g++) {
            s4[g] += __shfl_down_sync(0xffffffffu, s4[g], off);
            q4[g] += __shfl_down_sync(0xffffffffu, q4[g], off);
        }
    int wid = tid >> 5, lane = tid & 31;
    if (lane == 0) {
        #pragma unroll
        for (int g = 0; g < 4; g++) { rsm[wid][g] = s4[g]; rqm[wid][g] = q4[g]; }
    }
    __syncthreads();
    if (tid < 8) {
        int w0 = (tid < 4) ? 0 : 4, gl = tid & 3;
        float s = rsm[w0][gl] + rsm[w0+1][gl] + rsm[w0+2][gl] + rsm[w0+3][gl];
        float q = rqm[w0][gl] + rqm[w0+1][gl] + rqm[w0+2][gl] + rqm[w0+3][gl];
        atomicAdd(sac + b * 8 + tid, s);
        atomicAdd(qac + b * 8 + tid, q);
    }
}

__global__ void k_fin(const float* __restrict__ sac, const float* __restrict__ qac) {
    int i = threadIdx.x;
    if (i < 32) {
        float m = sac[i] * (1.f / 262144.f);
        float v = qac[i] * (1.f / 262144.f) - m * m;
        g_mu[i] = m; g_rs[i] = rsqrtf(v + EPS);
    }
}

__global__ void k_zero() {
    int t = blockIdx.x * 256 + threadIdx.x;           // 524288 threads, 4 float4 each
    float4 z = make_float4(0.f, 0.f, 0.f, 0.f);
    float4* p = (float4*)g_vox_a;
    p[t] = z; p[t + 524288] = z; p[t + 1048576] = z; p[t + 1572864] = z;
    if (t < 32768) ((int4*)g_cnt)[t] = make_int4(0, 0, 0, 0);
    if (t < 128) { g_sac[t] = 0.f; g_qac[t] = 0.f; }
}

__global__ void __launch_bounds__(128) k_scatter(const float* __restrict__ coords,
                                                 const float* __restrict__ gg,
                                                 const float* __restrict__ gb) {
    int p = blockIdx.x * 128 + threadIdx.x;
    int b = p >> 15, n = p & 32767;
    int ix = min(max(__float2int_rd(coords[p*3+0]*31.f), 0), 31);
    int iy = min(max(__float2int_rd(coords[p*3+1]*31.f), 0), 31);
    int iz = min(max(__float2int_rd(coords[p*3+2]*31.f), 0), 31);
    int flat = (ix << 10) + (iy << 5) + iz;
    atomicAdd(&g_cnt[(b << 15) + flat], 1);
    float* dst = g_vox_a + ((size_t)((b << 15) + flat) << 6);
    #pragma unroll 4
    for (int c = 0; c < CC; c++) {
        int bg = b * NG + (c >> 3);
        float x = g_pts[((b * CC + c) << 15) + n];
        x = siluf((x - g_mu[bg]) * g_rs[bg] * gg[c] + gb[c]) + g_bias[b * CC + c];
        atomicAdd(dst + c, x);
    }
}

__global__ void k_voxfin_cvt() {
    int idx = blockIdx.x * 256 + threadIdx.x;           // b*V3+v
    int b = idx >> 15;
    float inv = 1.f / (float)max(g_cnt[idx], 1);
    const float4* s4 = (const float4*)(g_vox_a + ((size_t)idx << 6));
    uint4* h4 = (uint4*)(g_hi + ((size_t)idx << 6));
    uint4* l4 = (uint4*)(g_lo + ((size_t)idx << 6));
    const float* bias = g_bias + b * CC;
    #pragma unroll
    for (int q = 0; q < 8; q++) {
        float4 v0 = s4[q*2], v1 = s4[q*2+1];
        float x[8] = {v0.x,v0.y,v0.z,v0.w,v1.x,v1.y,v1.z,v1.w};
        unsigned short hs[8], ls[8];
        #pragma unroll
        for (int j = 0; j < 8; j++) hi_lo(x[j]*inv + bias[q*8+j], hs[j], ls[j]);
        h4[q] = make_uint4(hs[0]|((uint32_t)hs[1]<<16), hs[2]|((uint32_t)hs[3]<<16),
                           hs[4]|((uint32_t)hs[5]<<16), hs[6]|((uint32_t)hs[7]<<16));
        l4[q] = make_uint4(ls[0]|((uint32_t)ls[1]<<16), ls[2]|((uint32_t)ls[3]<<16),
                           ls[4]|((uint32_t)ls[5]<<16), ls[6]|((uint32_t)ls[7]<<16));
    }
}

__global__ void k_gnsilu_cvt(const float* __restrict__ src,
                             const float* __restrict__ gg, const float* __restrict__ gb) {
    int idx = blockIdx.x * 256 + threadIdx.x;
    int b = idx >> 15;
    const float4* s4 = (const float4*)(src + ((size_t)idx << 6));
    uint4* h4 = (uint4*)(g_hi + ((size_t)idx << 6));
    uint4* l4 = (uint4*)(g_lo + ((size_t)idx << 6));
    #pragma unroll
    for (int q = 0; q < 8; q++) {
        float mu = g_mu[b*NG+q], rs = g_rs[b*NG+q];
        float4 v0 = s4[q*2], v1 = s4[q*2+1];
        float x[8] = {v0.x,v0.y,v0.z,v0.w,v1.x,v1.y,v1.z,v1.w};
        unsigned short hs[8], ls[8];
        #pragma unroll
        for (int j = 0; j < 8; j++) {
            int c = q*8+j;
            hi_lo(siluf((x[j]-mu)*rs*gg[c] + gb[c]), hs[j], ls[j]);
        }
        h4[q] = make_uint4(hs[0]|((uint32_t)hs[1]<<16), hs[2]|((uint32_t)hs[3]<<16),
                           hs[4]|((uint32_t)hs[5]<<16), hs[6]|((uint32_t)hs[7]<<16));
        l4[q] = make_uint4(ls[0]|((uint32_t)ls[1]<<16), ls[2]|((uint32_t)ls[3]<<16),
                           ls[4]|((uint32_t)ls[5]<<16), ls[6]|((uint32_t)ls[7]<<16));
    }
}

__global__ void k_gnsilu_vc(float* __restrict__ buf,
                            const float* __restrict__ gg, const float* __restrict__ gb) {
    int idx = blockIdx.x * 256 + threadIdx.x;
    int b = idx >> 15;
    float4* s4 = (float4*)(buf + ((size_t)idx << 6));
    #pragma unroll
    for (int q = 0; q < 8; q++) {
        float mu = g_mu[b*NG+q], rs = g_rs[b*NG+q];
        float4 v0 = s4[q*2], v1 = s4[q*2+1];
        float x[8] = {v0.x,v0.y,v0.z,v0.w,v1.x,v1.y,v1.z,v1.w};
        #pragma unroll
        for (int j = 0; j < 8; j++) {
            int c = q*8+j;
            x[j] = siluf((x[j]-mu)*rs*gg[c] + gb[c]);
        }
        s4[q*2]   = make_float4(x[0],x[1],x[2],x[3]);
        s4[q*2+1] = make_float4(x[4],x[5],x[6],x[7]);
    }
}

// wblob: B matrix per tap: row k = c_in (64 rows x 128B), col n = o_out, SW128 swizzled.
__global__ void k_wprep(const float* __restrict__ w1, const float* __restrict__ w2) {
    int i = blockIdx.x * 256 + threadIdx.x;
    if (i >= 221184) return;
    int conv = i / 110592, r = i - conv * 110592;
    int o = r / 1728, r2 = r - o * 1728;
    int c = r2 / 27, t = r2 - c * 27;
    float w = conv ? w2[r] : w1[r];
    __half h = __float2half_rn(w);
    __half l = __float2half_rn(w - __half2float(h));
    uint32_t off = (uint32_t)c * 128 + (uint32_t)o * 2;
    uint32_t swo = off ^ ((off >> 3) & 0x70);
    size_t base = (size_t)conv * 442368;
    *(__half*)(g_wblob + base + (size_t)t * 8192 + swo) = h;
    *(__half*)(g_wblob + base + 221184 + (size_t)t * 8192 + swo) = l;
}

// ---------------- HMMA conv: cp.async pipelined, 256 thr, 3 W buffers, fused stats ----------------
// smem: A hi [0, 26112) = 204 rows(6y x 34x) x 128B; A lo [26112, 52224);
//       W slots [52224 + s*16384): hi 8KB | lo 8KB, s = 0..2
#define CONV_SMEM 101376

__global__ void __launch_bounds__(256, 2)
k_conv_mma(const __half* __restrict__ hi, const __half* __restrict__ lo,
           const unsigned char* __restrict__ wblob, float* __restrict__ out,
           float* __restrict__ sac, float* __restrict__ qac) {
    extern __shared__ char smem[];
    const uint32_t sb = s2u(smem);
    const int tid = threadIdx.x, wid = tid >> 5, lane = tid & 31;
    int t = blockIdx.x;                     // b*256 + d*8 + hg
    int b = t >> 8, tt = t & 255;
    int d = tt >> 3, h0 = (tt & 7) << 2;
    int r0 = t << 7;                        // base output voxel index (b,v)

    int dzlist[3]; int ndz = 0;
    #pragma unroll
    for (int dz = 0; dz < 3; dz++) { int dp = d + dz - 1; if ((unsigned)dp < 32u) dzlist[ndz++] = dz; }
    int ntaps = ndz * 9;

    float acc[8][4];
    #pragma unroll
    for (int nt = 0; nt < 8; nt++)
        #pragma unroll
        for (int k = 0; k < 4; k++) acc[nt][k] = 0.f;

    const int a_r  = lane & 15;
    const int a_cb = (lane >> 4) << 4;

    auto stage_w = [&](int i) {
        int tap = dzlist[i / 9] * 9 + (i % 9);
        const unsigned char* wh = wblob + (size_t)tap * 8192;
        const unsigned char* wl = wblob + 221184 + (size_t)tap * 8192;
        uint32_t dst = sb + 52224 + (uint32_t)(i % 3) * 16384;
        int j0 = tid << 4, j1 = (tid + 256) << 4;
        cp16(dst + j0, wh + j0);
        cp16(dst + j1, wh + j1);
        cp16(dst + 8192 + j0, wl + j0);
        cp16(dst + 8192 + j1, wl + j1);
    };

    stage_w(0); CP_COMMIT();

    for (int s = 0; s < ndz; s++) {
        int dp = d + dzlist[s] - 1;
        __syncthreads();
        for (int i = tid; i < 1632; i += 256) {
            int row = i >> 3, c16 = i & 7;
            int yyl = row / 34, xl = row - yyl * 34;
            int hh = h0 + yyl - 1, ww = xl - 1;
            bool ok = ((unsigned)hh < 32u) && ((unsigned)ww < 32u);
            size_t g = ok ? (((size_t)((b << 15) + (dp << 10) + (hh << 5) + ww) << 3) + c16) : 0;
            uint32_t doff = (uint32_t)row * 128 + ((c16 << 4) ^ ((row & 7) << 4));
            cp16z(sb + doff,         (const uint4*)hi + g, ok);
            cp16z(sb + 26112 + doff, (const uint4*)lo + g, ok);
        }
        CP_COMMIT();
        for (int t9 = 0; t9 < 9; t9++) {
            int i = s * 9 + t9;
            if (i + 1 < ntaps) stage_w(i + 1);
            CP_COMMIT();
            CP_WAIT(1);
            __syncthreads();
            uint32_t wbase = sb + 52224 + (uint32_t)(i % 3) * 16384;
            int dy = t9 / 3 - 1, dx = t9 - (t9 / 3) * 3 - 1;
            int srow_base = ((wid >> 1) + dy + 1) * 34 + ((wid & 1) << 4) + dx + 1;
            #pragma unroll
            for (int ks = 0; ks < 4; ks++) {
                uint32_t Ah[4], Al[4], Bh[8][2], Bl[8][2];
                {
                    int row = srow_base + a_r;
                    uint32_t sw = (uint32_t)(((ks << 5) + a_cb) ^ ((row & 7) << 4));
                    uint32_t addr = sb + (uint32_t)row * 128 + sw;
                    LDSM4(Ah, addr);
                    LDSM4(Al, addr + 26112);
                }
                {
                    int krow = (ks << 4) + (lane & 15);
                    uint32_t rbase = wbase + (uint32_t)krow * 128;
                    uint32_t xr = (uint32_t)((krow & 7) << 4);
                    int nbl = (lane >> 4) << 4;
                    #pragma unroll
                    for (int nt4 = 0; nt4 < 4; nt4++) {
                        uint32_t nb = (uint32_t)((nt4 << 5) + nbl);
                        uint32_t addr = rbase + (nb ^ xr);
                        LDSM4T(Bh[nt4*2][0], Bh[nt4*2][1], Bh[nt4*2+1][0], Bh[nt4*2+1][1], addr);
                        LDSM4T(Bl[nt4*2][0], Bl[nt4*2][1], Bl[nt4*2+1][0], Bl[nt4*2+1][1], addr + 8192);
                    }
                }
                #pragma unroll
                for (int nt = 0; nt < 8; nt++) {
                    MMA(acc[nt], Ah, Bh[nt]);
                    MMA(acc[nt], Ah, Bl[nt]);
                    MMA(acc[nt], Al, Bh[nt]);
                }
            }
        }
    }
    // fused stats: nt == group; 4 values per nt per thread
    __syncthreads();
    {
        float s8[8], q8[8];
        #pragma unroll
        for (int nt = 0; nt < 8; nt++) {
            s8[nt] = acc[nt][0] + acc[nt][1] + acc[nt][2] + acc[nt][3];
            q8[nt] = acc[nt][0]*acc[nt][0] + acc[nt][1]*acc[nt][1]
                   + acc[nt][2]*acc[nt][2] + acc[nt][3]*acc[nt][3];
        }
        #pragma unroll
        for (int off = 16; off > 0; off >>= 1)
            #pragma unroll
            for (int g = 0; g < 8; g++) {
                s8[g] += __shfl_down_sync(0xffffffffu, s8[g], off);
                q8[g] += __shfl_down_sync(0xffffffffu, q8[g], off);
            }
        float* rsm = (float*)(smem + 52224);
        if (lane == 0) {
            #pragma unroll
            for (int g = 0; g < 8; g++) { rsm[wid*16+g] = s8[g]; rsm[wid*16+8+g] = q8[g]; }
        }
        __syncthreads();
        if (tid < 16) {
            float tsum = 0.f;
            #pragma unroll
            for (int w = 0; w < 8; w++) tsum += rsm[w*16+tid];
            if (tid < 8) atomicAdd(sac + b * 8 + tid, tsum);
            else         atomicAdd(qac + b * 8 + (tid - 8), tsum);
        }
    }
    // epilogue: write fp32 (b,v,c); warp owns 16 voxels
    int g = lane >> 2, tg = lane & 3;
    int v0 = r0 + (wid << 4) + g;
    #pragma unroll
    for (int nt = 0; nt < 8; nt++) {
        int c = (nt << 3) + tg * 2;
        float* o = out + ((size_t)v0 << 6) + c;
        o[0] = acc[nt][0];
        o[1] = acc[nt][1];
        o[512] = acc[nt][2];
        o[513] = acc[nt][3];
    }
}

// ---------------- devox + fuse: 256 thr, 2 threads/point, fused GN4 stats (pass 3) ----------------
__global__ void __launch_bounds__(256) k_devox(const float* __restrict__ coords,
                                               const float* __restrict__ wfuse,
                                               float* __restrict__ sac, float* __restrict__ qac) {
    __shared__ float swf[CC * CC];
    __shared__ float rsm[8][4], rqm[8][4];
    int tid = threadIdx.x;
    for (int i = tid; i < CC * CC; i += 256) swf[(i & 63) * CC + (i >> 6)] = wfuse[i];
    __syncthreads();
    int half = tid >> 7;
    int p = blockIdx.x * 128 + (tid & 127);
    int b = p >> 15, n = p & 32767;
    int o0 = half << 5;
    float cx = coords[p*3+0]*31.f, cy = coords[p*3+1]*31.f, cz = coords[p*3+2]*31.f;
    float fx = cx - floorf(cx), fy = cy - floorf(cy), fz = cz - floorf(cz);
    int x0 = min(max(__float2int_rd(cx),0),31), x1 = min(x0+1,31);
    int y0 = min(max(__float2int_rd(cy),0),31), y1 = min(y0+1,31);
    int z0 = min(max(__float2int_rd(cz),0),31), z1 = min(z0+1,31);
    const float4* base[8]; float wk[8]; int k = 0;
    #pragma unroll
    for (int ddx = 0; ddx < 2; ddx++)
        #pragma unroll
        for (int ddy = 0; ddy < 2; ddy++)
            #pragma unroll
            for (int ddz = 0; ddz < 2; ddz++) {
                int X = ddx?x1:x0, Y = ddy?y1:y0, Z = ddz?z1:z0;
                wk[k] = (ddx?fx:1.f-fx)*(ddy?fy:1.f-fy)*(ddz?fz:1.f-fz);
                base[k] = (const float4*)(g_vox_b + (((size_t)(b<<15) + ((X<<10)+(Y<<5)+Z)) << 6));
                k++;
            }
    float acc[32];
    #pragma unroll
    for (int o = 0; o < 32; o++) acc[o] = 0.f;
    #pragma unroll
    for (int c4 = 0; c4 < 16; c4++) {
        float r[32];
        #pragma unroll
        for (int kk = 0; kk < 8; kk++) {
            float4 v = __ldg(base[kk] + c4);
            r[kk*4] = v.x; r[kk*4+1] = v.y; r[kk*4+2] = v.z; r[kk*4+3] = v.w;
        }
        #pragma unroll
        for (int j = 0; j < 4; j++) {
            float dd = r[j]*wk[0] + r[4+j]*wk[1] + r[8+j]*wk[2] + r[12+j]*wk[3]
                     + r[16+j]*wk[4] + r[20+j]*wk[5] + r[24+j]*wk[6] + r[28+j]*wk[7];
            const float4* wr = (const float4*)(swf + (c4*4+j)*CC + o0);
            #pragma unroll
            for (int q = 0; q < 8; q++) {
                float4 ww = wr[q];
                acc[q*4+0] += dd*ww.x; acc[q*4+1] += dd*ww.y; acc[q*4+2] += dd*ww.z; acc[q*4+3] += dd*ww.w;
            }
        }
    }
    #pragma unroll
    for (int o = 0; o < 32; o++) g_pts[((b * CC + o0 + o) << 15) + n] = acc[o];
    // fused stats (groups half*4 .. +3)
    float s4[4], q4[4];
    #pragma unroll
    for (int g = 0; g < 4; g++) {
        float s = 0.f, q = 0.f;
        #pragma unroll
        for (int j = 0; j < 8; j++) { float v = acc[g*8+j]; s += v; q += v*v; }
        s4[g] = s; q4[g] = q;
    }
    #pragma unroll
    for (int off = 16; off > 0; off >>= 1)
        #pragma unroll
        for (int g = 0; g < 4; g++) {
            s4[g] += __shfl_down_sync(0xffffffffu, s4[g], off);
            q4[g] += __shfl_down_sync(0xffffffffu, q4[g], off);
        }
    int wid = tid >> 5, lane = tid & 31;
    if (lane == 0) {
        #pragma unroll
        for (int g = 0; g < 4; g++) { rsm[wid][g] = s4[g]; rqm[wid][g] = q4[g]; }
    }
    __syncthreads();
    if (tid < 8) {
        int w0 = (tid < 4) ? 0 : 4, gl = tid & 3;
        float s = rsm[w0][gl] + rsm[w0+1][gl] + rsm[w0+2][gl] + rsm[w0+3][gl];
        float q = rqm[w0][gl] + rqm[w0+1][gl] + rqm[w0+2][gl] + rqm[w0+3][gl];
        atomicAdd(sac + b * 8 + tid, s);
        atomicAdd(qac + b * 8 + tid, q);
    }
}

// final: 256 thr, 2 threads/point (32 out-ch each)
__global__ void __launch_bounds__(256) k_final(const float* __restrict__ f,
                                               const float* __restrict__ wskip,
                                               const float* __restrict__ gg,
                                               const float* __restrict__ gb,
                                               float* __restrict__ out) {
    __shared__ float sw[CIN * CC];
    __shared__ float sg[64], sb2[64];
    int tid = threadIdx.x;
    for (int i = tid; i < CIN * CC; i += 256) sw[(i & 31) * CC + (i >> 5)] = wskip[i];
    if (tid < 64) { sg[tid] = gg[tid]; sb2[tid] = gb[tid]; }
    __syncthreads();
    int half = tid >> 7;
    int p = blockIdx.x * 128 + (tid & 127);
    int b = p >> 15, n = p & 32767;
    int o0 = half << 5;
    float acc[32];
    #pragma unroll
    for (int o = 0; o < 32; o++) acc[o] = 0.f;
    for (int c = 0; c < CIN; c++) {
        float x = f[((b * CIN + c) << 15) + n];
        const float4* wr = (const float4*)(sw + c * CC + o0);
        #pragma unroll
        for (int q = 0; q < 8; q++) {
            float4 ww = wr[q];
            acc[q*4+0] += x*ww.x; acc[q*4+1] += x*ww.y; acc[q*4+2] += x*ww.z; acc[q*4+3] += x*ww.w;
        }
    }
    #pragma unroll
    for (int o = 0; o < 32; o++) {
        int oc = o0 + o;
        int bg = b * NG + (oc >> 3);
        float v = g_pts[((b * CC + oc) << 15) + n];
        v = (v - g_mu[bg]) * g_rs[bg] * sg[oc] + sb2[oc];
        out[((b * CC + oc) << 15) + n] = siluf(v) + acc[o];
    }
}

// ---------------------------------------------------------------------------
extern "C" void kernel_launch(void* const* d_in, const int* in_sizes, int n_in,
                              void* d_out, int out_size) {
    const float* feats  = (const float*)d_in[0];
    const float* coords = (const float*)d_in[1];
    const float* t_emb  = (const float*)d_in[2];
    const float* w_in   = (const float*)d_in[3];
    const float* gn1_g  = (const float*)d_in[4];
    const float* gn1_b  = (const float*)d_in[5];
    const float* w_time = (const float*)d_in[6];
    const float* b_time = (const float*)d_in[7];
    const float* w_vox1 = (const float*)d_in[8];
    const float* gn2_g  = (const float*)d_in[9];
    const float* gn2_b  = (const float*)d_in[10];
    const float* w_vox2 = (const float*)d_in[11];
    const float* gn3_g  = (const float*)d_in[12];
    const float* gn3_b  = (const float*)d_in[13];
    const float* w_fuse = (const float*)d_in[14];
    const float* gn4_g  = (const float*)d_in[15];
    const float* gn4_b  = (const float*)d_in[16];
    const float* w_skip = (const float*)d_in[17];
    float* out = (float*)d_out;

    float *pts, *va, *vb, *sac, *qac;
    __half *hp, *lp;
    unsigned char* wb;
    cudaGetSymbolAddress((void**)&pts, g_pts);
    cudaGetSymbolAddress((void**)&va, g_vox_a);
    cudaGetSymbolAddress((void**)&vb, g_vox_b);
    cudaGetSymbolAddress((void**)&hp, g_hi);
    cudaGetSymbolAddress((void**)&lp, g_lo);
    cudaGetSymbolAddress((void**)&wb, g_wblob);
    cudaGetSymbolAddress((void**)&sac, g_sac);
    cudaGetSymbolAddress((void**)&qac, g_qac);

    static int attr_set = 0;
    if (!attr_set) {
        cudaFuncSetAttribute(k_conv_mma, cudaFuncAttributeMaxDynamicSharedMemorySize, CONV_SMEM);
        attr_set = 1;
    }

    k_zero<<<2048, 256>>>();
    k_bias<<<NB, 64>>>(t_emb, w_time, b_time);
    k_wprep<<<864, 256>>>(w_vox1, w_vox2);
    k_pw_in<<<1024, 256>>>(feats, w_in, sac, qac);
    k_fin<<<1, 32>>>(sac, qac);
    k_scatter<<<1024, 128>>>(coords, gn1_g, gn1_b);
    k_voxfin_cvt<<<512, 256>>>();
    k_conv_mma<<<1024, 256, CONV_SMEM>>>(hp, lp, wb, va, sac + 32, qac + 32);
    k_fin<<<1, 32>>>(sac + 32, qac + 32);
    k_gnsilu_cvt<<<512, 256>>>(va, gn2_g, gn2_b);
    k_conv_mma<<<1024, 256, CONV_SMEM>>>(hp, lp, wb + 442368, vb, sac + 64, qac + 64);
    k_fin<<<1, 32>>>(sac + 64, qac + 64);
    k_gnsilu_vc<<<512, 256>>>(vb, gn3_g, gn3_b);
    k_devox<<<1024, 256>>>(coords, w_fuse, sac + 96, qac + 96);
    k_fin<<<1, 32>>>(sac + 96, qac + 96);
    k_final<<<1024, 256>>>(feats, w_skip, gn4_g, gn4_b, out);
}

// round 9
// speedup vs baseline: 1.4659x; 1.1486x over previous
#include <cuda_runtime.h>
#include <cuda_fp16.h>
#include <cstdint>

#define NB   4
#define CIN  32
#define CC   64
#define V3   32768
#define NG   8
#define EPS  1e-5f

__device__ __align__(16) float g_pts[NB * CC * V3];
__device__ __align__(16) float g_vox_a[NB * V3 * CC];
__device__ __align__(16) float g_vox_b[NB * V3 * CC];
__device__ __align__(16) __half g_hi[NB * V3 * CC];
__device__ __align__(16) __half g_lo[NB * V3 * CC];
__device__ __align__(16) unsigned char g_wblob[442368];  // [conv][tap][64x128B sw128] hi only
__device__ int   g_cnt[NB * V3];
__device__ float g_bias[NB * CC];
__device__ float g_mu[NB * NG];
__device__ float g_rs[NB * NG];
__device__ float g_sac[128];   // 4 passes x 32 (b,g) sums
__device__ float g_qac[128];   // sumsq

__device__ __forceinline__ float siluf(float x) { return x / (1.f + __expf(-x)); }

__device__ __forceinline__ uint32_t s2u(const void* p) {
    uint32_t a;
    asm("{ .reg .u64 t; cvta.to.shared.u64 t, %1; cvt.u32.u64 %0, t; }" : "=r"(a) : "l"(p));
    return a;
}

#define LDSM4(R, addr) \
    asm volatile("ldmatrix.sync.aligned.m8n8.x4.shared.b16 {%0,%1,%2,%3}, [%4];" \
        : "=r"((R)[0]), "=r"((R)[1]), "=r"((R)[2]), "=r"((R)[3]) : "r"(addr))
#define LDSM4T(r0, r1, r2, r3, addr) \
    asm volatile("ldmatrix.sync.aligned.m8n8.x4.trans.shared.b16 {%0,%1,%2,%3}, [%4];" \
        : "=r"(r0), "=r"(r1), "=r"(r2), "=r"(r3) : "r"(addr))
#define MMA(dacc, A, B) \
    asm volatile("mma.sync.aligned.m16n8k16.row.col.f32.f16.f16.f32 " \
        "{%0,%1,%2,%3}, {%4,%5,%6,%7}, {%8,%9}, {%0,%1,%2,%3};" \
        : "+f"((dacc)[0]), "+f"((dacc)[1]), "+f"((dacc)[2]), "+f"((dacc)[3]) \
        : "r"((A)[0]), "r"((A)[1]), "r"((A)[2]), "r"((A)[3]), "r"((B)[0]), "r"((B)[1]))

__device__ __forceinline__ void cp16(uint32_t dst, const void* src) {
    asm volatile("cp.async.cg.shared.global [%0], [%1], 16;" :: "r"(dst), "l"(src));
}
__device__ __forceinline__ void cp16z(uint32_t dst, const void* src, bool ok) {
    int sz = ok ? 16 : 0;
    asm volatile("cp.async.cg.shared.global [%0], [%1], 16, %2;" :: "r"(dst), "l"(src), "r"(sz));
}
#define CP_COMMIT() asm volatile("cp.async.commit_group;" ::: "memory")
#define CP_WAIT(n)  asm volatile("cp.async.wait_group %0;" :: "n"(n) : "memory")

__device__ __forceinline__ void hi_lo(float v, unsigned short& h, unsigned short& l) {
    __half hb = __float2half_rn(v);
    h = __half_as_ushort(hb);
    l = __half_as_ushort(__float2half_rn(v - __half2float(hb)));
}

// ---------------- small kernels ----------------
__global__ void k_bias(const float* __restrict__ te_, const float* __restrict__ wt,
                       const float* __restrict__ bt) {
    __shared__ float te[256];
    int b = blockIdx.x, o = threadIdx.x;
    for (int i = o; i < 256; i += 64) te[i] = te_[b * 256 + i];
    __syncthreads();
    float s = bt[o];
    #pragma unroll 8
    for (int t = 0; t < 256; t++) s += te[t] * wt[o * 256 + t];
    g_bias[b * CC + o] = s;
}

// pw_in: 256 thr, 2 threads/point (32 out-ch each), fused GN1 stats (pass 0)
__global__ void __launch_bounds__(256) k_pw_in(const float* __restrict__ f,
                                               const float* __restrict__ w,
                                               float* __restrict__ sac, float* __restrict__ qac) {
    __shared__ float sw[CIN * CC];
    __shared__ float rsm[8][4], rqm[8][4];
    int tid = threadIdx.x;
    for (int i = tid; i < CIN * CC; i += 256) sw[(i & 31) * CC + (i >> 5)] = w[i];
    __syncthreads();
    int half = tid >> 7;
    int p = blockIdx.x * 128 + (tid & 127);
    int b = p >> 15, n = p & 32767;
    int o0 = half << 5;
    float acc[32];
    #pragma unroll
    for (int o = 0; o < 32; o++) acc[o] = 0.f;
    for (int c = 0; c < CIN; c++) {
        float x = f[((b * CIN + c) << 15) + n];
        const float4* wr = (const float4*)(sw + c * CC + o0);
        #pragma unroll
        for (int q = 0; q < 8; q++) {
            float4 ww = wr[q];
            acc[q*4+0] += x*ww.x; acc[q*4+1] += x*ww.y; acc[q*4+2] += x*ww.z; acc[q*4+3] += x*ww.w;
        }
    }
    #pragma unroll
    for (int o = 0; o < 32; o++) g_pts[((b * CC + o0 + o) << 15) + n] = acc[o];
    float s4[4], q4[4];
    #pragma unroll
    for (int g = 0; g < 4; g++) {
        float s = 0.f, q = 0.f;
        #pragma unroll
        for (int j = 0; j < 8; j++) { float v = acc[g*8+j]; s += v; q += v*v; }
        s4[g] = s; q4[g] = q;
    }
    #pragma unroll
    for (int off = 16; off > 0; off >>= 1)
        #pragma unroll
        for (int g = 0; g < 4; g++) {
            s4[g] += __shfl_down_sync(0xffffffffu, s4[g], off);
            q4[g] += __shfl_down_sync(0xffffffffu, q4[g], off);
        }
    int wid = tid >> 5, lane = tid & 31;
    if (lane == 0) {
        #pragma unroll
        for (int g = 0; g < 4; g++) { rsm[wid][g] = s4[g]; rqm[wid][g] = q4[g]; }
    }
    __syncthreads();
    if (tid < 8) {
        int w0 = (tid < 4) ? 0 : 4, gl = tid & 3;
        float s = rsm[w0][gl] + rsm[w0+1][gl] + rsm[w0+2][gl] + rsm[w0+3][gl];
        float q = rqm[w0][gl] + rqm[w0+1][gl] + rqm[w0+2][gl] + rqm[w0+3][gl];
        atomicAdd(sac + b * 8 + tid, s);
        atomicAdd(qac + b * 8 + tid, q);
    }
}

__global__ void k_fin(const float* __restrict__ sac, const float* __restrict__ qac) {
    int i = threadIdx.x;
    if (i < 32) {
        float m = sac[i] * (1.f / 262144.f);
        float v = qac[i] * (1.f / 262144.f) - m * m;
        g_mu[i] = m; g_rs[i] = rsqrtf(v + EPS);
    }
}

__global__ void k_zero() {
    int t = blockIdx.x * 256 + threadIdx.x;
    float4 z = make_float4(0.f, 0.f, 0.f, 0.f);
    float4* p = (float4*)g_vox_a;
    p[t] = z; p[t + 524288] = z; p[t + 1048576] = z; p[t + 1572864] = z;
    if (t < 32768) ((int4*)g_cnt)[t] = make_int4(0, 0, 0, 0);
    if (t < 128) { g_sac[t] = 0.f; g_qac[t] = 0.f; }
}

__global__ void __launch_bounds__(128) k_scatter(const float* __restrict__ coords,
                                                 const float* __restrict__ gg,
                                                 const float* __restrict__ gb) {
    int p = blockIdx.x * 128 + threadIdx.x;
    int b = p >> 15, n = p & 32767;
    int ix = min(max(__float2int_rd(coords[p*3+0]*31.f), 0), 31);
    int iy = min(max(__float2int_rd(coords[p*3+1]*31.f), 0), 31);
    int iz = min(max(__float2int_rd(coords[p*3+2]*31.f), 0), 31);
    int flat = (ix << 10) + (iy << 5) + iz;
    atomicAdd(&g_cnt[(b << 15) + flat], 1);
    float* dst = g_vox_a + ((size_t)((b << 15) + flat) << 6);
    #pragma unroll 4
    for (int c = 0; c < CC; c++) {
        int bg = b * NG + (c >> 3);
        float x = g_pts[((b * CC + c) << 15) + n];
        x = siluf((x - g_mu[bg]) * g_rs[bg] * gg[c] + gb[c]) + g_bias[b * CC + c];
        atomicAdd(dst + c, x);
    }
}

__global__ void k_voxfin_cvt() {
    int idx = blockIdx.x * 256 + threadIdx.x;
    int b = idx >> 15;
    float inv = 1.f / (float)max(g_cnt[idx], 1);
    const float4* s4 = (const float4*)(g_vox_a + ((size_t)idx << 6));
    uint4* h4 = (uint4*)(g_hi + ((size_t)idx << 6));
    uint4* l4 = (uint4*)(g_lo + ((size_t)idx << 6));
    const float* bias = g_bias + b * CC;
    #pragma unroll
    for (int q = 0; q < 8; q++) {
        float4 v0 = s4[q*2], v1 = s4[q*2+1];
        float x[8] = {v0.x,v0.y,v0.z,v0.w,v1.x,v1.y,v1.z,v1.w};
        unsigned short hs[8], ls[8];
        #pragma unroll
        for (int j = 0; j < 8; j++) hi_lo(x[j]*inv + bias[q*8+j], hs[j], ls[j]);
        h4[q] = make_uint4(hs[0]|((uint32_t)hs[1]<<16), hs[2]|((uint32_t)hs[3]<<16),
                           hs[4]|((uint32_t)hs[5]<<16), hs[6]|((uint32_t)hs[7]<<16));
        l4[q] = make_uint4(ls[0]|((uint32_t)ls[1]<<16), ls[2]|((uint32_t)ls[3]<<16),
                           ls[4]|((uint32_t)ls[5]<<16), ls[6]|((uint32_t)ls[7]<<16));
    }
}

__global__ void k_gnsilu_cvt(const float* __restrict__ src,
                             const float* __restrict__ gg, const float* __restrict__ gb) {
    int idx = blockIdx.x * 256 + threadIdx.x;
    int b = idx >> 15;
    const float4* s4 = (const float4*)(src + ((size_t)idx << 6));
    uint4* h4 = (uint4*)(g_hi + ((size_t)idx << 6));
    uint4* l4 = (uint4*)(g_lo + ((size_t)idx << 6));
    #pragma unroll
    for (int q = 0; q < 8; q++) {
        float mu = g_mu[b*NG+q], rs = g_rs[b*NG+q];
        float4 v0 = s4[q*2], v1 = s4[q*2+1];
        float x[8] = {v0.x,v0.y,v0.z,v0.w,v1.x,v1.y,v1.z,v1.w};
        unsigned short hs[8], ls[8];
        #pragma unroll
        for (int j = 0; j < 8; j++) {
            int c = q*8+j;
            hi_lo(siluf((x[j]-mu)*rs*gg[c] + gb[c]), hs[j], ls[j]);
        }
        h4[q] = make_uint4(hs[0]|((uint32_t)hs[1]<<16), hs[2]|((uint32_t)hs[3]<<16),
                           hs[4]|((uint32_t)hs[5]<<16), hs[6]|((uint32_t)hs[7]<<16));
        l4[q] = make_uint4(ls[0]|((uint32_t)ls[1]<<16), ls[2]|((uint32_t)ls[3]<<16),
                           ls[4]|((uint32_t)ls[5]<<16), ls[6]|((uint32_t)ls[7]<<16));
    }
}

__global__ void k_gnsilu_vc(float* __restrict__ buf,
                            const float* __restrict__ gg, const float* __restrict__ gb) {
    int idx = blockIdx.x * 256 + threadIdx.x;
    int b = idx >> 15;
    float4* s4 = (float4*)(buf + ((size_t)idx << 6));
    #pragma unroll
    for (int q = 0; q < 8; q++) {
        float mu = g_mu[b*NG+q], rs = g_rs[b*NG+q];
        float4 v0 = s4[q*2], v1 = s4[q*2+1];
        float x[8] = {v0.x,v0.y,v0.z,v0.w,v1.x,v1.y,v1.z,v1.w};
        #pragma unroll
        for (int j = 0; j < 8; j++) {
            int c = q*8+j;
            x[j] = siluf((x[j]-mu)*rs*gg[c] + gb[c]);
        }
        s4[q*2]   = make_float4(x[0],x[1],x[2],x[3]);
        s4[q*2+1] = make_float4(x[4],x[5],x[6],x[7]);
    }
}

// wblob: B matrix per tap (hi only): row k = c_in (64 x 128B), col n = o_out, SW128.
__global__ void k_wprep(const float* __restrict__ w1, const float* __restrict__ w2) {
    int i = blockIdx.x * 256 + threadIdx.x;
    if (i >= 221184) return;
    int conv = i / 110592, r = i - conv * 110592;
    int o = r / 1728, r2 = r - o * 1728;
    int c = r2 / 27, t = r2 - c * 27;
    float w = conv ? w2[r] : w1[r];
    __half h = __float2half_rn(w);
    uint32_t off = (uint32_t)c * 128 + (uint32_t)o * 2;
    uint32_t swo = off ^ ((off >> 3) & 0x70);
    *(__half*)(g_wblob + (size_t)conv * 221184 + (size_t)t * 8192 + swo) = h;
}

// ---------------- HMMA conv: 2-pass (A hi+lo, W hi), cp.async pipelined ----------------
// smem: A hi [0, 26112) = 204 rows(6y x 34x) x 128B; A lo [26112, 52224);
//       W slots [52224 + s*8192), s = 0..2
#define CONV_SMEM 76800

__global__ void __launch_bounds__(256, 2)
k_conv_mma(const __half* __restrict__ hi, const __half* __restrict__ lo,
           const unsigned char* __restrict__ wblob, float* __restrict__ out,
           float* __restrict__ sac, float* __restrict__ qac) {
    extern __shared__ char smem[];
    const uint32_t sb = s2u(smem);
    const int tid = threadIdx.x, wid = tid >> 5, lane = tid & 31;
    int t = blockIdx.x;                     // b*256 + d*8 + hg
    int b = t >> 8, tt = t & 255;
    int d = tt >> 3, h0 = (tt & 7) << 2;
    int r0 = t << 7;

    int dzlist[3]; int ndz = 0;
    #pragma unroll
    for (int dz = 0; dz < 3; dz++) { int dp = d + dz - 1; if ((unsigned)dp < 32u) dzlist[ndz++] = dz; }
    int ntaps = ndz * 9;

    float acc[8][4];
    #pragma unroll
    for (int nt = 0; nt < 8; nt++)
        #pragma unroll
        for (int k = 0; k < 4; k++) acc[nt][k] = 0.f;

    const int a_r  = lane & 15;
    const int a_cb = (lane >> 4) << 4;

    auto stage_w = [&](int i) {
        int tap = dzlist[i / 9] * 9 + (i % 9);
        const unsigned char* wh = wblob + (size_t)tap * 8192;
        uint32_t dst = sb + 52224 + (uint32_t)(i % 3) * 8192;
        int j0 = tid << 4, j1 = (tid + 256) << 4;
        cp16(dst + j0, wh + j0);
        cp16(dst + j1, wh + j1);
    };

    stage_w(0); CP_COMMIT();

    for (int s = 0; s < ndz; s++) {
        int dp = d + dzlist[s] - 1;
        __syncthreads();
        for (int i = tid; i < 1632; i += 256) {
            int row = i >> 3, c16 = i & 7;
            int yyl = row / 34, xl = row - yyl * 34;
            int hh = h0 + yyl - 1, ww = xl - 1;
            bool ok = ((unsigned)hh < 32u) && ((unsigned)ww < 32u);
            size_t g = ok ? (((size_t)((b << 15) + (dp << 10) + (hh << 5) + ww) << 3) + c16) : 0;
            uint32_t doff = (uint32_t)row * 128 + ((c16 << 4) ^ ((row & 7) << 4));
            cp16z(sb + doff,         (const uint4*)hi + g, ok);
            cp16z(sb + 26112 + doff, (const uint4*)lo + g, ok);
        }
        CP_COMMIT();
        for (int t9 = 0; t9 < 9; t9++) {
            int i = s * 9 + t9;
            if (i + 1 < ntaps) stage_w(i + 1);
            CP_COMMIT();
            CP_WAIT(1);
            __syncthreads();
            uint32_t wbase = sb + 52224 + (uint32_t)(i % 3) * 8192;
            int dy = t9 / 3 - 1, dx = t9 - (t9 / 3) * 3 - 1;
            int srow_base = ((wid >> 1) + dy + 1) * 34 + ((wid & 1) << 4) + dx + 1;
            #pragma unroll
            for (int ks = 0; ks < 4; ks++) {
                uint32_t Ah[4], Al[4], Bh[8][2];
                {
                    int row = srow_base + a_r;
                    uint32_t sw = (uint32_t)(((ks << 5) + a_cb) ^ ((row & 7) << 4));
                    uint32_t addr = sb + (uint32_t)row * 128 + sw;
                    LDSM4(Ah, addr);
                    LDSM4(Al, addr + 26112);
                }
                {
                    int krow = (ks << 4) + (lane & 15);
                    uint32_t rbase = wbase + (uint32_t)krow * 128;
                    uint32_t xr = (uint32_t)((krow & 7) << 4);
                    int nbl = (lane >> 4) << 4;
                    #pragma unroll
                    for (int nt4 = 0; nt4 < 4; nt4++) {
                        uint32_t nb = (uint32_t)((nt4 << 5) + nbl);
                        uint32_t addr = rbase + (nb ^ xr);
                        LDSM4T(Bh[nt4*2][0], Bh[nt4*2][1], Bh[nt4*2+1][0], Bh[nt4*2+1][1], addr);
                    }
                }
                #pragma unroll
                for (int nt = 0; nt < 8; nt++) {
                    MMA(acc[nt], Ah, Bh[nt]);
                    MMA(acc[nt], Al, Bh[nt]);
                }
            }
        }
    }
    // fused stats
    __syncthreads();
    {
        float s8[8], q8[8];
        #pragma unroll
        for (int nt = 0; nt < 8; nt++) {
            s8[nt] = acc[nt][0] + acc[nt][1] + acc[nt][2] + acc[nt][3];
            q8[nt] = acc[nt][0]*acc[nt][0] + acc[nt][1]*acc[nt][1]
                   + acc[nt][2]*acc[nt][2] + acc[nt][3]*acc[nt][3];
        }
        #pragma unroll
        for (int off = 16; off > 0; off >>= 1)
            #pragma unroll
            for (int g = 0; g < 8; g++) {
                s8[g] += __shfl_down_sync(0xffffffffu, s8[g], off);
                q8[g] += __shfl_down_sync(0xffffffffu, q8[g], off);
            }
        float* rsm = (float*)(smem + 52224);
        if (lane == 0) {
            #pragma unroll
            for (int g = 0; g < 8; g++) { rsm[wid*16+g] = s8[g]; rsm[wid*16+8+g] = q8[g]; }
        }
        __syncthreads();
        if (tid < 16) {
            float tsum = 0.f;
            #pragma unroll
            for (int w = 0; w < 8; w++) tsum += rsm[w*16+tid];
            if (tid < 8) atomicAdd(sac + b * 8 + tid, tsum);
            else         atomicAdd(qac + b * 8 + (tid - 8), tsum);
        }
    }
    // epilogue
    int g = lane >> 2, tg = lane & 3;
    int v0 = r0 + (wid << 4) + g;
    #pragma unroll
    for (int nt = 0; nt < 8; nt++) {
        int c = (nt << 3) + tg * 2;
        float* o = out + ((size_t)v0 << 6) + c;
        o[0] = acc[nt][0];
        o[1] = acc[nt][1];
        o[512] = acc[nt][2];
        o[513] = acc[nt][3];
    }
}

// ---------------- devox + fuse: 256 thr, fused GN4 stats ----------------
__global__ void __launch_bounds__(256) k_devox(const float* __restrict__ coords,
                                               const float* __restrict__ wfuse,
                                               float* __restrict__ sac, float* __restrict__ qac) {
    __shared__ float swf[CC * CC];
    __shared__ float rsm[8][4], rqm[8][4];
    int tid = threadIdx.x;
    for (int i = tid; i < CC * CC; i += 256) swf[(i & 63) * CC + (i >> 6)] = wfuse[i];
    __syncthreads();
    int half = tid >> 7;
    int p = blockIdx.x * 128 + (tid & 127);
    int b = p >> 15, n = p & 32767;
    int o0 = half << 5;
    float cx = coords[p*3+0]*31.f, cy = coords[p*3+1]*31.f, cz = coords[p*3+2]*31.f;
    float fx = cx - floorf(cx), fy = cy - floorf(cy), fz = cz - floorf(cz);
    int x0 = min(max(__float2int_rd(cx),0),31), x1 = min(x0+1,31);
    int y0 = min(max(__float2int_rd(cy),0),31), y1 = min(y0+1,31);
    int z0 = min(max(__float2int_rd(cz),0),31), z1 = min(z0+1,31);
    const float4* base[8]; float wk[8]; int k = 0;
    #pragma unroll
    for (int ddx = 0; ddx < 2; ddx++)
        #pragma unroll
        for (int ddy = 0; ddy < 2; ddy++)
            #pragma unroll
            for (int ddz = 0; ddz < 2; ddz++) {
                int X = ddx?x1:x0, Y = ddy?y1:y0, Z = ddz?z1:z0;
                wk[k] = (ddx?fx:1.f-fx)*(ddy?fy:1.f-fy)*(ddz?fz:1.f-fz);
                base[k] = (const float4*)(g_vox_b + (((size_t)(b<<15) + ((X<<10)+(Y<<5)+Z)) << 6));
                k++;
            }
    float acc[32];
    #pragma unroll
    for (int o = 0; o < 32; o++) acc[o] = 0.f;
    #pragma unroll
    for (int c4 = 0; c4 < 16; c4++) {
        float r[32];
        #pragma unroll
        for (int kk = 0; kk < 8; kk++) {
            float4 v = __ldg(base[kk] + c4);
            r[kk*4] = v.x; r[kk*4+1] = v.y; r[kk*4+2] = v.z; r[kk*4+3] = v.w;
        }
        #pragma unroll
        for (int j = 0; j < 4; j++) {
            float dd = r[j]*wk[0] + r[4+j]*wk[1] + r[8+j]*wk[2] + r[12+j]*wk[3]
                     + r[16+j]*wk[4] + r[20+j]*wk[5] + r[24+j]*wk[6] + r[28+j]*wk[7];
            const float4* wr = (const float4*)(swf + (c4*4+j)*CC + o0);
            #pragma unroll
            for (int q = 0; q < 8; q++) {
                float4 ww = wr[q];
                acc[q*4+0] += dd*ww.x; acc[q*4+1] += dd*ww.y; acc[q*4+2] += dd*ww.z; acc[q*4+3] += dd*ww.w;
            }
        }
    }
    #pragma unroll
    for (int o = 0; o < 32; o++) g_pts[((b * CC + o0 + o) << 15) + n] = acc[o];
    float s4[4], q4[4];
    #pragma unroll
    for (int g = 0; g < 4; g++) {
        float s = 0.f, q = 0.f;
        #pragma unroll
        for (int j = 0; j < 8; j++) { float v = acc[g*8+j]; s += v; q += v*v; }
        s4[g] = s; q4[g] = q;
    }
    #pragma unroll
    for (int off = 16; off > 0; off >>= 1)
        #pragma unroll
        for (int g = 0; g < 4; g++) {
            s4[g] += __shfl_down_sync(0xffffffffu, s4[g], off);
            q4[g] += __shfl_down_sync(0xffffffffu, q4[g], off);
        }
    int wid = tid >> 5, lane = tid & 31;
    if (lane == 0) {
        #pragma unroll
        for (int g = 0; g < 4; g++) { rsm[wid][g] = s4[g]; rqm[wid][g] = q4[g]; }
    }
    __syncthreads();
    if (tid < 8) {
        int w0 = (tid < 4) ? 0 : 4, gl = tid & 3;
        float s = rsm[w0][gl] + rsm[w0+1][gl] + rsm[w0+2][gl] + rsm[w0+3][gl];
        float q = rqm[w0][gl] + rqm[w0+1][gl] + rqm[w0+2][gl] + rqm[w0+3][gl];
        atomicAdd(sac + b * 8 + tid, s);
        atomicAdd(qac + b * 8 + tid, q);
    }
}

// final: 256 thr, 2 threads/point
__global__ void __launch_bounds__(256) k_final(const float* __restrict__ f,
                                               const float* __restrict__ wskip,
                                               const float* __restrict__ gg,
                                               const float* __restrict__ gb,
                                               float* __restrict__ out) {
    __shared__ float sw[CIN * CC];
    __shared__ float sg[64], sb2[64];
    int tid = threadIdx.x;
    for (int i = tid; i < CIN * CC; i += 256) sw[(i & 31) * CC + (i >> 5)] = wskip[i];
    if (tid < 64) { sg[tid] = gg[tid]; sb2[tid] = gb[tid]; }
    __syncthreads();
    int half = tid >> 7;
    int p = blockIdx.x * 128 + (tid & 127);
    int b = p >> 15, n = p & 32767;
    int o0 = half << 5;
    float acc[32];
    #pragma unroll
    for (int o = 0; o < 32; o++) acc[o] = 0.f;
    for (int c = 0; c < CIN; c++) {
        float x = f[((b * CIN + c) << 15) + n];
        const float4* wr = (const float4*)(sw + c * CC + o0);
        #pragma unroll
        for (int q = 0; q < 8; q++) {
            float4 ww = wr[q];
            acc[q*4+0] += x*ww.x; acc[q*4+1] += x*ww.y; acc[q*4+2] += x*ww.z; acc[q*4+3] += x*ww.w;
        }
    }
    #pragma unroll
    for (int o = 0; o < 32; o++) {
        int oc = o0 + o;
        int bg = b * NG + (oc >> 3);
        float v = g_pts[((b * CC + oc) << 15) + n];
        v = (v - g_mu[bg]) * g_rs[bg] * sg[oc] + sb2[oc];
        out[((b * CC + oc) << 15) + n] = siluf(v) + acc[o];
    }
}

// ---------------------------------------------------------------------------
extern "C" void kernel_launch(void* const* d_in, const int* in_sizes, int n_in,
                              void* d_out, int out_size) {
    const float* feats  = (const float*)d_in[0];
    const float* coords = (const float*)d_in[1];
    const float* t_emb  = (const float*)d_in[2];
    const float* w_in   = (const float*)d_in[3];
    const float* gn1_g  = (const float*)d_in[4];
    const float* gn1_b  = (const float*)d_in[5];
    const float* w_time = (const float*)d_in[6];
    const float* b_time = (const float*)d_in[7];
    const float* w_vox1 = (const float*)d_in[8];
    const float* gn2_g  = (const float*)d_in[9];
    const float* gn2_b  = (const float*)d_in[10];
    const float* w_vox2 = (const float*)d_in[11];
    const float* gn3_g  = (const float*)d_in[12];
    const float* gn3_b  = (const float*)d_in[13];
    const float* w_fuse = (const float*)d_in[14];
    const float* gn4_g  = (const float*)d_in[15];
    const float* gn4_b  = (const float*)d_in[16];
    const float* w_skip = (const float*)d_in[17];
    float* out = (float*)d_out;

    float *pts, *va, *vb, *sac, *qac;
    __half *hp, *lp;
    unsigned char* wb;
    cudaGetSymbolAddress((void**)&pts, g_pts);
    cudaGetSymbolAddress((void**)&va, g_vox_a);
    cudaGetSymbolAddress((void**)&vb, g_vox_b);
    cudaGetSymbolAddress((void**)&hp, g_hi);
    cudaGetSymbolAddress((void**)&lp, g_lo);
    cudaGetSymbolAddress((void**)&wb, g_wblob);
    cudaGetSymbolAddress((void**)&sac, g_sac);
    cudaGetSymbolAddress((void**)&qac, g_qac);

    static int attr_set = 0;
    if (!attr_set) {
        cudaFuncSetAttribute(k_conv_mma, cudaFuncAttributeMaxDynamicSharedMemorySize, CONV_SMEM);
        attr_set = 1;
    }

    k_zero<<<2048, 256>>>();
    k_bias<<<NB, 64>>>(t_emb, w_time, b_time);
    k_wprep<<<864, 256>>>(w_vox1, w_vox2);
    k_pw_in<<<1024, 256>>>(feats, w_in, sac, qac);
    k_fin<<<1, 32>>>(sac, qac);
    k_scatter<<<1024, 128>>>(coords, gn1_g, gn1_b);
    k_voxfin_cvt<<<512, 256>>>();
    k_conv_mma<<<1024, 256, CONV_SMEM>>>(hp, lp, wb, va, sac + 32, qac + 32);
    k_fin<<<1, 32>>>(sac + 32, qac + 32);
    k_gnsilu_cvt<<<512, 256>>>(va, gn2_g, gn2_b);
    k_conv_mma<<<1024, 256, CONV_SMEM>>>(hp, lp, wb + 221184, vb, sac + 64, qac + 64);
    k_fin<<<1, 32>>>(sac + 64, qac + 64);
    k_gnsilu_vc<<<512, 256>>>(vb, gn3_g, gn3_b);
    k_devox<<<1024, 256>>>(coords, w_fuse, sac + 96, qac + 96);
    k_fin<<<1, 32>>>(sac + 96, qac + 96);
    k_final<<<1024, 256>>>(feats, w_skip, gn4_g, gn4_b, out);
}